// round 14
// baseline (speedup 1.0000x reference)
#include <cuda_runtime.h>
#include <cuda_bf16.h>
#include <math.h>
#include <stdint.h>

typedef __nv_bfloat16 bf16;

// ---------------- constants ----------------
#define DIMC   1024
#define TEMBC  512
#define NTOK   3456
#define TENC   128
#define WQN    5
#define LWIN   1280
#define SROW   576
#define MQ     6400
#define MFF    3584
#define HEADS_ 16
#define HD_    64
#define QKVN   3072
#define MEG    1048576

// ---------------- device scratch ----------------
__device__ float g_emb1[6144];
__device__ float g_emb2[6144];
__device__ bf16  g_x   [(size_t)MFF * DIMC];   // x rows; later reused as blended ao
__device__ bf16  g_qkv [(size_t)MFF * QKVN];
__device__ bf16  g_ao  [(size_t)MQ * DIMC];
__device__ float g_o2  [(size_t)MFF * DIMC];   // split-K partial 0
__device__ float g_p1  [(size_t)MFF * DIMC];   // split-K partial 1
__device__ bf16  g_ffin[(size_t)MFF * DIMC];
__device__ bf16  g_h1  [(size_t)MFF * 4096];
__device__ bf16  g_wt  [(size_t)12 * MEG];     // qkv^T(3M), wo^T(1M), w1^T(4M), w2^T(4M)

__constant__ float c_pyr[8] = {1.f,2.f,3.f,4.f,4.f,3.f,2.f,1.f};

// ---------------- helpers ----------------
__device__ __forceinline__ uint32_t pack_bf2(float lo, float hi) {
    uint32_t r;
    asm("cvt.rn.bf16x2.f32 %0, %1, %2;" : "=r"(r) : "f"(hi), "f"(lo));
    return r;
}

__device__ __forceinline__ uint32_t smem_u32(const void* p) {
    return (uint32_t)__cvta_generic_to_shared(p);
}

__device__ __forceinline__ void block_reduce_2(float &s, float &s2) {
    __shared__ float ra[8], rb[8];
#pragma unroll
    for (int m = 16; m > 0; m >>= 1) {
        s  += __shfl_xor_sync(0xffffffffu, s,  m);
        s2 += __shfl_xor_sync(0xffffffffu, s2, m);
    }
    int wid = threadIdx.x >> 5;
    if ((threadIdx.x & 31) == 0) { ra[wid] = s; rb[wid] = s2; }
    __syncthreads();
    s  = ra[0]+ra[1]+ra[2]+ra[3]+ra[4]+ra[5]+ra[6]+ra[7];
    s2 = rb[0]+rb[1]+rb[2]+rb[3]+rb[4]+rb[5]+rb[6]+rb[7];
    __syncthreads();
}

__device__ __forceinline__ float tanh_fast(float x) {
    float y;
    asm("tanh.approx.f32 %0, %1;" : "=f"(y) : "f"(x));
    return y;
}

__device__ __forceinline__ float gelu_tanh(float x) {
    float x3 = x * x * x;
    return 0.5f * x * (1.f + tanh_fast(0.79788456080286535588f * (x + 0.044715f * x3)));
}

__device__ __forceinline__ void mma_bf16(float* d, const uint32_t* a, const uint32_t* b) {
    asm volatile(
        "mma.sync.aligned.m16n8k16.row.col.f32.bf16.bf16.f32 "
        "{%0,%1,%2,%3}, {%4,%5,%6,%7}, {%8,%9}, {%0,%1,%2,%3};"
        : "+f"(d[0]), "+f"(d[1]), "+f"(d[2]), "+f"(d[3])
        : "r"(a[0]), "r"(a[1]), "r"(a[2]), "r"(a[3]), "r"(b[0]), "r"(b[1]));
}

// ---------------- weight prep: transpose + round to bf16 ----------------
__global__ __launch_bounds__(256) void round_wT4_kernel(
    const float* __restrict__ w0, const float* __restrict__ w1,
    const float* __restrict__ w2, const float* __restrict__ w3,
    bf16* __restrict__ dst)
{
    __shared__ float t[32][33];
    int z = blockIdx.z;
    const float* W = (z == 0) ? w0 : (z == 1) ? w1 : (z == 2) ? w2 : w3;
    bf16* WT = dst + (size_t)z * MEG;
    int n0 = blockIdx.x * 32, k0 = blockIdx.y * 32;
    int tx = threadIdx.x, ty = threadIdx.y;
#pragma unroll
    for (int j = 0; j < 4; j++)
        t[ty + 8 * j][tx] = W[(size_t)(k0 + ty + 8 * j) * 1024 + n0 + tx];
    __syncthreads();
#pragma unroll
    for (int j = 0; j < 4; j++)
        WT[(size_t)(n0 + ty + 8 * j) * 1024 + k0 + tx] =
            __float2bfloat16_rn(t[tx][ty + 8 * j]);
}

__global__ __launch_bounds__(256) void round_wT2_kernel(
    const float* __restrict__ w1, bf16* __restrict__ wt1,
    const float* __restrict__ w2, bf16* __restrict__ wt2)
{
    __shared__ float t[32][33];
    const float* W; bf16* WT; int K, N, n0, k0;
    if (blockIdx.z == 0) {
        W = w1; WT = wt1; K = 1024; N = 4096;
        n0 = blockIdx.x * 32; k0 = blockIdx.y * 32;
    } else {
        W = w2; WT = wt2; K = 4096; N = 1024;
        int lin = blockIdx.x * 32 + blockIdx.y;   // 0..4095
        n0 = (lin & 31) * 32; k0 = (lin >> 5) * 32;
    }
    int tx = threadIdx.x, ty = threadIdx.y;
#pragma unroll
    for (int j = 0; j < 4; j++)
        t[ty + 8 * j][tx] = W[(size_t)(k0 + ty + 8 * j) * N + n0 + tx];
    __syncthreads();
#pragma unroll
    for (int j = 0; j < 4; j++)
        WT[(size_t)(n0 + ty + 8 * j) * K + k0 + tx] =
            __float2bfloat16_rn(t[tx][ty + 8 * j]);
}

// ---------------- emb = silu(temb) @ W + b  (high-occupancy) ----------------
__global__ __launch_bounds__(256) void emb2_kernel(
    const float* __restrict__ temb,
    const float* __restrict__ w1, const float* __restrict__ b1,
    const float* __restrict__ w2, const float* __restrict__ b2)
{
    __shared__ float st[TEMBC];
    __shared__ float part[8][32];
    int tid = threadIdx.x, lane = tid & 31, wid = tid >> 5;
    for (int i = tid; i < TEMBC; i += 256) {
        float t = temb[i];
        st[i] = t / (1.f + expf(-t));
    }
    __syncthreads();

    int colg = blockIdx.x * 32;
    const float* w; const float* bb; float* out; int col;
    if (colg < 6144) { w = w1; bb = b1; out = g_emb1; col = colg + lane; }
    else             { w = w2; bb = b2; out = g_emb2; col = colg - 6144 + lane; }

    float acc = 0.f;
    int k0 = wid * 64;
#pragma unroll 16
    for (int kk = 0; kk < 64; kk++)
        acc += st[k0 + kk] * w[(size_t)(k0 + kk) * 6144 + col];
    part[wid][lane] = acc;
    __syncthreads();
    if (wid == 0) {
        float s = 0.f;
#pragma unroll
        for (int i = 0; i < 8; i++) s += part[i][lane];
        out[col] = s + bb[col];
    }
}

// ---------------- build unique x rows (bf16 out) ----------------
__global__ __launch_bounds__(256) void build_x_kernel(
    const float* __restrict__ hs, const float* __restrict__ enc,
    const float* __restrict__ g, const float* __restrict__ b)
{
    int row = blockIdx.x;
    const float* src; int sc_off, sh_off;
    if (row < TENC) { src = enc + (size_t)row * DIMC; sc_off = 4096; sh_off = 3072; }
    else            { src = hs + (size_t)(row - TENC) * DIMC; sc_off = 1024; sh_off = 0; }
    int tid = threadIdx.x;
    float x[4]; float s = 0.f, s2 = 0.f;
#pragma unroll
    for (int i = 0; i < 4; i++) {
        x[i] = src[tid + i * 256];
        s += x[i]; s2 += x[i] * x[i];
    }
    block_reduce_2(s, s2);
    float mean = s * (1.f / DIMC);
    float var  = s2 * (1.f / DIMC) - mean * mean;
    float inv  = rsqrtf(var + 1e-5f);
    bf16* dst = g_x + (size_t)row * DIMC;
#pragma unroll
    for (int i = 0; i < 4; i++) {
        int d = tid + i * 256;
        float v = (x[i] - mean) * inv * g[d] + b[d];
        dst[d] = __float2bfloat16_rn(v * (1.f + g_emb1[sc_off + d]) + g_emb1[sh_off + d]);
    }
}

// ---------------- BF16 tensor-core GEMM, 3-stage ring, optional split-K -------
// flags: 1=gelu, 2=bf16 out, 8=split-K partial (f32, no bias; z picks P0/P1)
#define SSTR 72
#define STAGE_B 18432
#define GEMM_SMEM_B (6 * STAGE_B)      // 110592 B

__global__ __launch_bounds__(256, 2) void gemm_bf16_kernel(
    const bf16* __restrict__ A, const bf16* __restrict__ B,
    const float* __restrict__ bias, void* __restrict__ Cv, void* __restrict__ Cv2,
    int M, int N, int K, int klen, int flags)
{
    extern __shared__ bf16 smb[];
    bf16* As0 = smb;
    bf16* Bs0 = smb + 3 * 128 * SSTR;

    int tid = threadIdx.x;
    int bm = blockIdx.y, bn = blockIdx.x, kz = blockIdx.z;
    int lane = tid & 31, wid = tid >> 5;
    int wm = (wid & 1) * 64, wn = (wid >> 1) * 32;
    int gid = lane >> 2, tig = lane & 3;
    int kstart = kz * klen;

    const bf16* Ag = A + (size_t)bm * 128 * K + kstart;
    const bf16* Bg = B + (size_t)bn * 128 * K + kstart;

    uint32_t smbase = smem_u32(smb);
    uint32_t aBase0 = smbase + (uint32_t)((wm + (lane & 15)) * 144 + (lane >> 4) * 16);
    uint32_t bBase0 = smbase + 3u * STAGE_B +
                      (uint32_t)((wn + (lane & 7) + ((lane >> 4) << 3)) * 144 +
                                 ((lane >> 3) & 1) * 16);

    float acc[4][4][4];
#pragma unroll
    for (int a = 0; a < 4; a++)
#pragma unroll
        for (int b = 0; b < 4; b++)
#pragma unroll
            for (int c = 0; c < 4; c++) acc[a][b][c] = 0.f;

#define LOAD_TILE(kt, buf)                                                         \
    {                                                                              \
        bf16* ad = As0 + (buf) * 128 * SSTR;                                       \
        bf16* bd = Bs0 + (buf) * 128 * SSTR;                                       \
        _Pragma("unroll")                                                          \
        for (int i = 0; i < 4; i++) {                                              \
            int c = tid + i * 256;                                                 \
            int r = c >> 3, kc = (c & 7) << 3;                                     \
            uint32_t dsm = (uint32_t)__cvta_generic_to_shared(ad + r * SSTR + kc); \
            const bf16* s = Ag + (size_t)r * K + (kt) * 64 + kc;                   \
            asm volatile("cp.async.cg.shared.global [%0], [%1], 16;"               \
                         :: "r"(dsm), "l"(s));                                     \
        }                                                                          \
        _Pragma("unroll")                                                          \
        for (int i = 0; i < 4; i++) {                                              \
            int c = tid + i * 256;                                                 \
            int r = c >> 3, kc = (c & 7) << 3;                                     \
            uint32_t dsm = (uint32_t)__cvta_generic_to_shared(bd + r * SSTR + kc); \
            const bf16* s = Bg + (size_t)r * K + (kt) * 64 + kc;                   \
            asm volatile("cp.async.cg.shared.global [%0], [%1], 16;"               \
                         :: "r"(dsm), "l"(s));                                     \
        }                                                                          \
    }

    int ktiles = klen / 64;
    LOAD_TILE(0, 0);
    asm volatile("cp.async.commit_group;");
    LOAD_TILE(1, 1);
    asm volatile("cp.async.commit_group;");

    int buf = 0;
    for (int t = 0; t < ktiles; t++) {
        if (t + 1 < ktiles) asm volatile("cp.async.wait_group 1;");
        else                asm volatile("cp.async.wait_group 0;");
        __syncthreads();
        if (t + 2 < ktiles) {
            int nb = (t + 2) % 3;
            LOAD_TILE(t + 2, nb);
            asm volatile("cp.async.commit_group;");
        }

        uint32_t aB = aBase0 + (uint32_t)buf * STAGE_B;
        uint32_t bB = bBase0 + (uint32_t)buf * STAGE_B;
#pragma unroll
        for (int ks = 0; ks < 4; ks++) {
            uint32_t af[4][4], bfr[2][4];
#pragma unroll
            for (int mt = 0; mt < 4; mt++)
                asm volatile(
                    "ldmatrix.sync.aligned.m8n8.x4.shared.b16 {%0,%1,%2,%3}, [%4];"
                    : "=r"(af[mt][0]), "=r"(af[mt][1]), "=r"(af[mt][2]), "=r"(af[mt][3])
                    : "r"(aB + mt * 2304 + ks * 32));
#pragma unroll
            for (int np = 0; np < 2; np++)
                asm volatile(
                    "ldmatrix.sync.aligned.m8n8.x4.shared.b16 {%0,%1,%2,%3}, [%4];"
                    : "=r"(bfr[np][0]), "=r"(bfr[np][1]), "=r"(bfr[np][2]), "=r"(bfr[np][3])
                    : "r"(bB + np * 2304 + ks * 32));
#pragma unroll
            for (int mt = 0; mt < 4; mt++) {
                mma_bf16(acc[mt][0], af[mt], &bfr[0][0]);
                mma_bf16(acc[mt][1], af[mt], &bfr[0][2]);
                mma_bf16(acc[mt][2], af[mt], &bfr[1][0]);
                mma_bf16(acc[mt][3], af[mt], &bfr[1][2]);
            }
        }
        buf = (buf == 2) ? 0 : buf + 1;
    }

    int act = flags & 1, outbf = flags & 2, spl = flags & 8;
    float* Csp = (float*)(kz ? Cv2 : Cv);
#pragma unroll
    for (int mt = 0; mt < 4; mt++) {
        int row = bm * 128 + wm + mt * 16 + gid;
#pragma unroll
        for (int nt = 0; nt < 4; nt++) {
            int col = bn * 128 + wn + nt * 8 + tig * 2;
            if (spl) {
                *(float2*)(Csp + (size_t)row * N + col) =
                    make_float2(acc[mt][nt][0], acc[mt][nt][1]);
                *(float2*)(Csp + (size_t)(row + 8) * N + col) =
                    make_float2(acc[mt][nt][2], acc[mt][nt][3]);
                continue;
            }
            float b0 = bias ? bias[col] : 0.f;
            float b1 = bias ? bias[col + 1] : 0.f;
            float v0 = acc[mt][nt][0] + b0, v1 = acc[mt][nt][1] + b1;
            float v2 = acc[mt][nt][2] + b0, v3 = acc[mt][nt][3] + b1;
            if (act) { v0 = gelu_tanh(v0); v1 = gelu_tanh(v1); v2 = gelu_tanh(v2); v3 = gelu_tanh(v3); }
            if (outbf) {
                bf16* C = (bf16*)Cv;
                *(uint32_t*)(C + (size_t)row * N + col)       = pack_bf2(v0, v1);
                *(uint32_t*)(C + (size_t)(row + 8) * N + col) = pack_bf2(v2, v3);
            } else {
                float* C = (float*)Cv;
                *(float2*)(C + (size_t)row * N + col)       = make_float2(v0, v1);
                *(float2*)(C + (size_t)(row + 8) * N + col) = make_float2(v2, v3);
            }
        }
    }
}

// ------- per-head LN on q and k in one launch (y: 0=q scale .125, 1=k) --------
__global__ __launch_bounds__(256) void qkln2_kernel(
    bf16* __restrict__ buf,
    const float* __restrict__ qg, const float* __restrict__ qb,
    const float* __restrict__ kg, const float* __restrict__ kb)
{
    int seg  = blockIdx.x * 8 + (threadIdx.x >> 5);
    int lane = threadIdx.x & 31;
    int isk  = blockIdx.y;
    const float* g = isk ? kg : qg;
    const float* b = isk ? kb : qb;
    float scale = isk ? 1.0f : 0.125f;
    bf16* p = buf + (size_t)(seg >> 4) * QKVN + isk * 1024 + (seg & 15) * HD_;
    float x0 = __bfloat162float(p[lane]);
    float x1 = __bfloat162float(p[lane + 32]);
    float s = x0 + x1, s2 = x0 * x0 + x1 * x1;
#pragma unroll
    for (int m = 16; m > 0; m >>= 1) {
        s  += __shfl_xor_sync(0xffffffffu, s,  m);
        s2 += __shfl_xor_sync(0xffffffffu, s2, m);
    }
    float mean = s * (1.f / 64.f);
    float var  = s2 * (1.f / 64.f) - mean * mean;
    float inv  = rsqrtf(var + 1e-6f);
    p[lane]      = __float2bfloat16_rn(((x0 - mean) * inv * g[lane]      + b[lane])      * scale);
    p[lane + 32] = __float2bfloat16_rn(((x1 - mean) * inv * g[lane + 32] + b[lane + 32]) * scale);
}

// ---------------- BF16 flash attention, 3-buffer cp.async KV ring -------------
#define KVSTAGE (64 * SSTR)
#define ATTN_SMEM_B ((128 * SSTR + 6 * KVSTAGE) * 2)   // 73728 B

__global__ __launch_bounds__(256, 2) void attn_bf16_kernel(
    const bf16* __restrict__ qkv, bf16* __restrict__ o)
{
    extern __shared__ bf16 smb[];
    bf16* Qs  = smb;
    bf16* Ks0 = smb + 128 * SSTR;
    bf16* Vs0 = Ks0 + 3 * KVSTAGE;

    int qt = blockIdx.x, h = blockIdx.y, w = blockIdx.z;
    int tid = threadIdx.x, lane = tid & 31, wid = tid >> 5;
    int gid = lane >> 2, tig = lane & 3;
    int wq0 = wid * 16;
    const size_t obase = (size_t)w * LWIN * DIMC + (size_t)h * HD_;

    size_t qrow0 = (size_t)qt * 128 + (qt ? (size_t)w * SROW : 0);
    const bf16* qg = qkv + qrow0 * QKVN + h * HD_;

#pragma unroll
    for (int i = 0; i < 4; i++) {
        int e = tid + i * 256;
        int r = e >> 3, dc = (e & 7) << 3;
        *(uint4*)(Qs + r * SSTR + dc) = *(const uint4*)(qg + (size_t)r * QKVN + dc);
    }

#define KV_LOAD(kt, buf)                                                           \
    {                                                                              \
        size_t krow0 = (size_t)(kt) * 64 + ((kt) >= 2 ? (size_t)w * SROW : 0);     \
        const bf16* kg = qkv + krow0 * QKVN + 1024 + h * HD_;                      \
        const bf16* vg = qkv + krow0 * QKVN + 2048 + h * HD_;                      \
        bf16* kd = Ks0 + (buf) * KVSTAGE;                                          \
        bf16* vd = Vs0 + (buf) * KVSTAGE;                                          \
        _Pragma("unroll")                                                          \
        for (int i = 0; i < 2; i++) {                                              \
            int e = tid + i * 256;                                                 \
            int r = e >> 3, dc = (e & 7) << 3;                                     \
            uint32_t dk = (uint32_t)__cvta_generic_to_shared(kd + r * SSTR + dc);  \
            uint32_t dv = (uint32_t)__cvta_generic_to_shared(vd + r * SSTR + dc);  \
            asm volatile("cp.async.cg.shared.global [%0], [%1], 16;"               \
                         :: "r"(dk), "l"(kg + (size_t)r * QKVN + dc));             \
            asm volatile("cp.async.cg.shared.global [%0], [%1], 16;"               \
                         :: "r"(dv), "l"(vg + (size_t)r * QKVN + dc));             \
        }                                                                          \
    }

    KV_LOAD(0, 0);
    asm volatile("cp.async.commit_group;");
    KV_LOAD(1, 1);
    asm volatile("cp.async.commit_group;");

    float accO[8][4];
#pragma unroll
    for (int nt = 0; nt < 8; nt++)
#pragma unroll
        for (int i = 0; i < 4; i++) accO[nt][i] = 0.f;
    float m0 = -1e30f, m1 = -1e30f, l0 = 0.f, l1 = 0.f;

    int buf = 0;
    for (int kt = 0; kt < 20; kt++) {
        if (kt + 1 < 20) asm volatile("cp.async.wait_group 1;");
        else             asm volatile("cp.async.wait_group 0;");
        __syncthreads();
        if (kt + 2 < 20) {
            int nb = (kt + 2) % 3;
            KV_LOAD(kt + 2, nb);
            asm volatile("cp.async.commit_group;");
        }

        const bf16* Ks = Ks0 + buf * KVSTAGE;
        const bf16* Vs = Vs0 + buf * KVSTAGE;

        float s[8][4];
#pragma unroll
        for (int nt = 0; nt < 8; nt++)
#pragma unroll
            for (int i = 0; i < 4; i++) s[nt][i] = 0.f;

        const uint32_t* Qw = (const uint32_t*)Qs;
        const uint32_t* Kw = (const uint32_t*)Ks;
#pragma unroll
        for (int ks = 0; ks < 4; ks++) {
            uint32_t af[4];
            int ai = (wq0 + gid) * 36 + ks * 8 + tig;
            af[0] = Qw[ai]; af[1] = Qw[ai + 288];
            af[2] = Qw[ai + 4]; af[3] = Qw[ai + 292];
#pragma unroll
            for (int nt = 0; nt < 8; nt++) {
                uint32_t bfr[2];
                int bi = (nt * 8 + gid) * 36 + ks * 8 + tig;
                bfr[0] = Kw[bi]; bfr[1] = Kw[bi + 4];
                mma_bf16(s[nt], af, bfr);
            }
        }

        float mx0 = -1e30f, mx1 = -1e30f;
#pragma unroll
        for (int nt = 0; nt < 8; nt++) {
            mx0 = fmaxf(mx0, fmaxf(s[nt][0], s[nt][1]));
            mx1 = fmaxf(mx1, fmaxf(s[nt][2], s[nt][3]));
        }
        mx0 = fmaxf(mx0, __shfl_xor_sync(0xffffffffu, mx0, 1));
        mx0 = fmaxf(mx0, __shfl_xor_sync(0xffffffffu, mx0, 2));
        mx1 = fmaxf(mx1, __shfl_xor_sync(0xffffffffu, mx1, 1));
        mx1 = fmaxf(mx1, __shfl_xor_sync(0xffffffffu, mx1, 2));
        float mn0 = fmaxf(m0, mx0), mn1 = fmaxf(m1, mx1);
        float f0 = __expf(m0 - mn0), f1 = __expf(m1 - mn1);
        m0 = mn0; m1 = mn1;
        float sum0 = 0.f, sum1 = 0.f;
#pragma unroll
        for (int nt = 0; nt < 8; nt++) {
            s[nt][0] = __expf(s[nt][0] - mn0);
            s[nt][1] = __expf(s[nt][1] - mn0);
            s[nt][2] = __expf(s[nt][2] - mn1);
            s[nt][3] = __expf(s[nt][3] - mn1);
            sum0 += s[nt][0] + s[nt][1];
            sum1 += s[nt][2] + s[nt][3];
        }
        sum0 += __shfl_xor_sync(0xffffffffu, sum0, 1);
        sum0 += __shfl_xor_sync(0xffffffffu, sum0, 2);
        sum1 += __shfl_xor_sync(0xffffffffu, sum1, 1);
        sum1 += __shfl_xor_sync(0xffffffffu, sum1, 2);
        l0 = l0 * f0 + sum0;
        l1 = l1 * f1 + sum1;
#pragma unroll
        for (int nt = 0; nt < 8; nt++) {
            accO[nt][0] *= f0; accO[nt][1] *= f0;
            accO[nt][2] *= f1; accO[nt][3] *= f1;
        }

#pragma unroll
        for (int kc = 0; kc < 4; kc++) {
            uint32_t aP[4];
            aP[0] = pack_bf2(s[2 * kc][0],     s[2 * kc][1]);
            aP[1] = pack_bf2(s[2 * kc][2],     s[2 * kc][3]);
            aP[2] = pack_bf2(s[2 * kc + 1][0], s[2 * kc + 1][1]);
            aP[3] = pack_bf2(s[2 * kc + 1][2], s[2 * kc + 1][3]);
#pragma unroll
            for (int ntp = 0; ntp < 4; ntp++) {
                int row = kc * 16 + ((lane >> 3) & 1) * 8 + (lane & 7);
                int col = ntp * 16 + (lane >> 4) * 8;
                uint32_t smaddr = smem_u32(Vs + row * SSTR + col);
                uint32_t b0, b1, b2, b3;
                asm volatile(
                    "ldmatrix.sync.aligned.m8n8.x4.trans.shared.b16 {%0,%1,%2,%3}, [%4];"
                    : "=r"(b0), "=r"(b1), "=r"(b2), "=r"(b3) : "r"(smaddr));
                uint32_t blo[2] = {b0, b1}, bhi[2] = {b2, b3};
                mma_bf16(accO[2 * ntp],     aP, blo);
                mma_bf16(accO[2 * ntp + 1], aP, bhi);
            }
        }
        buf = (buf == 2) ? 0 : buf + 1;
    }

    float il0 = 1.f / l0, il1 = 1.f / l1;
    int row0 = qt * 128 + wq0 + gid;
#pragma unroll
    for (int nt = 0; nt < 8; nt++) {
        int col = nt * 8 + tig * 2;
        *(uint32_t*)(o + obase + (size_t)row0 * DIMC + col) =
            pack_bf2(accO[nt][0] * il0, accO[nt][1] * il0);
        *(uint32_t*)(o + obase + (size_t)(row0 + 8) * DIMC + col) =
            pack_bf2(accO[nt][2] * il1, accO[nt][3] * il1);
    }
}

// ------- blend attention outputs across windows (before wo) -------------------
__global__ __launch_bounds__(256) void blend_ao_kernel()
{
    int row = blockIdx.x;            // 0..MFF-1
    int tid = threadIdx.x;
    bf16* dst = g_x + (size_t)row * DIMC;
    if (row < TENC) {
#pragma unroll
        for (int i = 0; i < 4; i++) {
            int d = tid + i * 256;
            float a = 0.f;
#pragma unroll
            for (int w = 0; w < WQN; w++)
                a += __bfloat162float(g_ao[((size_t)w * LWIN + row) * DIMC + d]);
            dst[d] = __float2bfloat16_rn(a * 0.2f);
        }
    } else {
        int gdx = row - TENC;
        int blk = gdx / SROW;
        float acc[4] = {0.f, 0.f, 0.f, 0.f};
        float wsum = 0.f;
#pragma unroll
        for (int dw = -1; dw <= 0; dw++) {
            int w = blk + dw;
            if (w < 0 || w > 4) continue;
            int lv = gdx - w * SROW;
            float wt = c_pyr[lv / 144];
            wsum += wt;
            const bf16* op = g_ao + ((size_t)w * LWIN + TENC + lv) * DIMC;
#pragma unroll
            for (int i = 0; i < 4; i++)
                acc[i] += wt * __bfloat162float(op[tid + i * 256]);
        }
        float inv = 1.f / wsum;
#pragma unroll
        for (int i = 0; i < 4; i++)
            dst[tid + i * 256] = __float2bfloat16_rn(acc[i] * inv);
    }
}

// ------- post-wo combine: residual(+split-K reduce + bias) + LN2 --------------
__global__ __launch_bounds__(256) void combine_post_kernel(
    const float* __restrict__ hs, const float* __restrict__ enc,
    float* __restrict__ out, const float* __restrict__ g, const float* __restrict__ b,
    const float* __restrict__ bo)
{
    int row = blockIdx.x;            // 0..MFF-1
    int tid = threadIdx.x;
    const float* p0 = g_o2 + (size_t)row * DIMC;
    const float* p1 = g_p1 + (size_t)row * DIMC;
    const float* src; float* outp; int gate_off, sc_off, sh_off;
    if (row < TENC) {
        src = enc + (size_t)row * DIMC;
        outp = out + (size_t)(NTOK + row) * DIMC;
        gate_off = 5120; sc_off = 4096; sh_off = 3072;
    } else {
        int gdx = row - TENC;
        src = hs + (size_t)gdx * DIMC;
        outp = out + (size_t)gdx * DIMC;
        gate_off = 2048; sc_off = 1024; sh_off = 0;
    }
    float r[4]; float s = 0.f, s2 = 0.f;
#pragma unroll
    for (int i = 0; i < 4; i++) {
        int d = tid + i * 256;
        float o2 = p0[d] + p1[d] + bo[d];
        r[i] = src[d] + g_emb1[gate_off + d] * o2;
        outp[d] = r[i];
        s += r[i]; s2 += r[i] * r[i];
    }
    block_reduce_2(s, s2);
    float mean = s * (1.f / DIMC);
    float var  = s2 * (1.f / DIMC) - mean * mean;
    float inv2 = rsqrtf(var + 1e-5f);
    bf16* dst = g_ffin + (size_t)row * DIMC;
#pragma unroll
    for (int i = 0; i < 4; i++) {
        int d = tid + i * 256;
        float v = (r[i] - mean) * inv2 * g[d] + b[d];
        dst[d] = __float2bfloat16_rn(v * (1.f + g_emb2[sc_off + d]) + g_emb2[sh_off + d]);
    }
}

// ------- ffn2 split-K finish: out += gate * (p0 + p1 + b) ---------------------
__global__ __launch_bounds__(256) void final_add_kernel(
    float* __restrict__ out, const float* __restrict__ ffb2)
{
    int row = blockIdx.x;            // 0..MFF-1
    int tid = threadIdx.x;
    const float* p0 = g_o2 + (size_t)row * DIMC;
    const float* p1 = g_p1 + (size_t)row * DIMC;
    float* outp; int gate_off;
    if (row < TENC) { outp = out + (size_t)(NTOK + row) * DIMC; gate_off = 5120; }
    else            { outp = out + (size_t)(row - TENC) * DIMC; gate_off = 2048; }
#pragma unroll
    for (int i = 0; i < 4; i++) {
        int d = tid + i * 256;
        outp[d] += g_emb2[gate_off + d] * (p0[d] + p1[d] + ffb2[d]);
    }
}

// ---------------- host side ----------------
static void launch_gemm(const bf16* A, const bf16* B, const float* bias,
                        void* C, void* C2, int M, int N, int K, int klen,
                        int gz, int flags)
{
    dim3 grid(N / 128, M / 128, gz);
    gemm_bf16_kernel<<<grid, 256, GEMM_SMEM_B>>>(A, B, bias, C, C2, M, N, K, klen, flags);
}

extern "C" void kernel_launch(void* const* d_in, const int* in_sizes, int n_in,
                              void* d_out, int out_size)
{
    const float* hs    = (const float*)d_in[0];
    const float* enc   = (const float*)d_in[1];
    const float* temb  = (const float*)d_in[2];
    const float* n1w   = (const float*)d_in[3];
    const float* n1b   = (const float*)d_in[4];
    const float* n1g   = (const float*)d_in[5];
    const float* n1bb  = (const float*)d_in[6];
    const float* wq    = (const float*)d_in[7];
    const float* wk    = (const float*)d_in[8];
    const float* wv    = (const float*)d_in[9];
    const float* nqg   = (const float*)d_in[10];
    const float* nqb   = (const float*)d_in[11];
    const float* nkg   = (const float*)d_in[12];
    const float* nkb   = (const float*)d_in[13];
    const float* wo    = (const float*)d_in[14];
    const float* bo    = (const float*)d_in[15];
    const float* n2w   = (const float*)d_in[16];
    const float* n2b   = (const float*)d_in[17];
    const float* n2g   = (const float*)d_in[18];
    const float* n2bb  = (const float*)d_in[19];
    const float* ffw1  = (const float*)d_in[20];
    const float* ffb1  = (const float*)d_in[21];
    const float* ffw2  = (const float*)d_in[22];
    const float* ffb2  = (const float*)d_in[23];
    (void)in_sizes; (void)n_in;

    float* out = (float*)d_out;
    (void)out_size;

    bf16 *p_x, *p_qkv, *p_ao, *p_ffin, *p_h1, *p_wt;
    float *p_o2, *p_p1;
    cudaGetSymbolAddress((void**)&p_x,    g_x);
    cudaGetSymbolAddress((void**)&p_qkv,  g_qkv);
    cudaGetSymbolAddress((void**)&p_ao,   g_ao);
    cudaGetSymbolAddress((void**)&p_o2,   g_o2);
    cudaGetSymbolAddress((void**)&p_p1,   g_p1);
    cudaGetSymbolAddress((void**)&p_ffin, g_ffin);
    cudaGetSymbolAddress((void**)&p_h1,   g_h1);
    cudaGetSymbolAddress((void**)&p_wt,   g_wt);

    bf16* wtqkv = p_wt;                       // [3072][1024] (wq^T|wk^T|wv^T)
    bf16* wtwo  = p_wt + (size_t)3 * MEG;     // [1024][1024]
    bf16* wtw1  = p_wt + (size_t)4 * MEG;     // [4096][1024]
    bf16* wtw2  = p_wt + (size_t)8 * MEG;     // [1024][4096]

    cudaFuncSetAttribute(attn_bf16_kernel, cudaFuncAttributeMaxDynamicSharedMemorySize, ATTN_SMEM_B);
    cudaFuncSetAttribute(gemm_bf16_kernel, cudaFuncAttributeMaxDynamicSharedMemorySize, GEMM_SMEM_B);

    // 0. weight prep
    dim3 tb(32, 8);
    round_wT4_kernel<<<dim3(32, 32, 4), tb>>>(wq, wk, wv, wo, wtqkv);
    round_wT2_kernel<<<dim3(128, 32, 2), tb>>>(ffw1, wtw1, ffw2, wtw2);

    // 1. modulation embeddings
    emb2_kernel<<<384, 256>>>(temb, n1w, n1b, n2w, n2b);
    // 2. unique x rows (bf16)
    build_x_kernel<<<MFF, 256>>>(hs, enc, n1g, n1bb);
    // 3. fused QKV projection -> bf16
    launch_gemm(p_x, wtqkv, nullptr, p_qkv, nullptr, MFF, QKVN, DIMC, DIMC, 1, 2);
    // 4. per-head LN on q (x0.125 folded) and k, one launch
    qkln2_kernel<<<dim3(MFF * HEADS_ / 8, 2), 256>>>(p_qkv, nqg, nqb, nkg, nkb);
    // 5. attention (3-buffer cp.async KV ring)
    attn_bf16_kernel<<<dim3(LWIN / 128, HEADS_, WQN), 256, ATTN_SMEM_B>>>(p_qkv, p_ao);
    // 6. blend windows BEFORE wo, then wo split-K (2 halves in one launch)
    blend_ao_kernel<<<MFF, 256>>>();
    launch_gemm(p_x, wtwo, nullptr, p_o2, p_p1, MFF, DIMC, DIMC, 512, 2, 8);
    // 7. residual (+wo reduce +bo) + LN2 -> out, ffin
    combine_post_kernel<<<MFF, 256>>>(hs, enc, out, n2g, n2bb, bo);
    // 8. FFN: ffn1 fused gelu->bf16; ffn2 split-K; finish adds gated residual
    launch_gemm(p_ffin, wtw1, ffb1, p_h1, nullptr, MFF, 4096, DIMC, DIMC, 1, 1 | 2);
    launch_gemm(p_h1, wtw2, nullptr, p_o2, p_p1, MFF, DIMC, 4096, 2048, 2, 8);
    final_add_kernel<<<MFF, 256>>>(out, ffb2);
}

// round 15
// speedup vs baseline: 1.0138x; 1.0138x over previous
#include <cuda_runtime.h>
#include <cuda_bf16.h>
#include <math.h>
#include <stdint.h>

typedef __nv_bfloat16 bf16;

// ---------------- constants ----------------
#define DIMC   1024
#define TEMBC  512
#define NTOK   3456
#define TENC   128
#define WQN    5
#define LWIN   1280
#define SROW   576
#define MQ     6400
#define MFF    3584
#define HEADS_ 16
#define HD_    64
#define QKVN   3072
#define MEG    1048576

// ---------------- device scratch ----------------
__device__ float g_emb1[6144];
__device__ float g_emb2[6144];
__device__ bf16  g_x   [(size_t)MFF * DIMC];   // x rows; later reused as blended ao
__device__ bf16  g_qkv [(size_t)MFF * QKVN];
__device__ bf16  g_ao  [(size_t)MQ * DIMC];
__device__ float g_o2  [(size_t)MFF * DIMC];
__device__ bf16  g_ffin[(size_t)MFF * DIMC];
__device__ bf16  g_h1  [(size_t)MFF * 4096];
__device__ bf16  g_wt  [(size_t)12 * MEG];     // qkv^T(3M), wo^T(1M), w1^T(4M), w2^T(4M)

__constant__ float c_pyr[8] = {1.f,2.f,3.f,4.f,4.f,3.f,2.f,1.f};

// ---------------- helpers ----------------
__device__ __forceinline__ uint32_t pack_bf2(float lo, float hi) {
    uint32_t r;
    asm("cvt.rn.bf16x2.f32 %0, %1, %2;" : "=r"(r) : "f"(hi), "f"(lo));
    return r;
}

__device__ __forceinline__ uint32_t smem_u32(const void* p) {
    return (uint32_t)__cvta_generic_to_shared(p);
}

__device__ __forceinline__ void block_reduce_2(float &s, float &s2) {
    __shared__ float ra[8], rb[8];
#pragma unroll
    for (int m = 16; m > 0; m >>= 1) {
        s  += __shfl_xor_sync(0xffffffffu, s,  m);
        s2 += __shfl_xor_sync(0xffffffffu, s2, m);
    }
    int wid = threadIdx.x >> 5;
    if ((threadIdx.x & 31) == 0) { ra[wid] = s; rb[wid] = s2; }
    __syncthreads();
    s  = ra[0]+ra[1]+ra[2]+ra[3]+ra[4]+ra[5]+ra[6]+ra[7];
    s2 = rb[0]+rb[1]+rb[2]+rb[3]+rb[4]+rb[5]+rb[6]+rb[7];
    __syncthreads();
}

__device__ __forceinline__ float tanh_fast(float x) {
    float y;
    asm("tanh.approx.f32 %0, %1;" : "=f"(y) : "f"(x));
    return y;
}

__device__ __forceinline__ float gelu_tanh(float x) {
    float x3 = x * x * x;
    return 0.5f * x * (1.f + tanh_fast(0.79788456080286535588f * (x + 0.044715f * x3)));
}

__device__ __forceinline__ void mma_bf16(float* d, const uint32_t* a, const uint32_t* b) {
    asm volatile(
        "mma.sync.aligned.m16n8k16.row.col.f32.bf16.bf16.f32 "
        "{%0,%1,%2,%3}, {%4,%5,%6,%7}, {%8,%9}, {%0,%1,%2,%3};"
        : "+f"(d[0]), "+f"(d[1]), "+f"(d[2]), "+f"(d[3])
        : "r"(a[0]), "r"(a[1]), "r"(a[2]), "r"(a[3]), "r"(b[0]), "r"(b[1]));
}

// ---------------- weight prep: transpose + round to bf16 ----------------
__global__ __launch_bounds__(256) void round_wT4_kernel(
    const float* __restrict__ w0, const float* __restrict__ w1,
    const float* __restrict__ w2, const float* __restrict__ w3,
    bf16* __restrict__ dst)
{
    __shared__ float t[32][33];
    int z = blockIdx.z;
    const float* W = (z == 0) ? w0 : (z == 1) ? w1 : (z == 2) ? w2 : w3;
    bf16* WT = dst + (size_t)z * MEG;
    int n0 = blockIdx.x * 32, k0 = blockIdx.y * 32;
    int tx = threadIdx.x, ty = threadIdx.y;
#pragma unroll
    for (int j = 0; j < 4; j++)
        t[ty + 8 * j][tx] = W[(size_t)(k0 + ty + 8 * j) * 1024 + n0 + tx];
    __syncthreads();
#pragma unroll
    for (int j = 0; j < 4; j++)
        WT[(size_t)(n0 + ty + 8 * j) * 1024 + k0 + tx] =
            __float2bfloat16_rn(t[tx][ty + 8 * j]);
}

__global__ __launch_bounds__(256) void round_wT2_kernel(
    const float* __restrict__ w1, bf16* __restrict__ wt1,
    const float* __restrict__ w2, bf16* __restrict__ wt2)
{
    __shared__ float t[32][33];
    const float* W; bf16* WT; int K, N, n0, k0;
    if (blockIdx.z == 0) {
        W = w1; WT = wt1; K = 1024; N = 4096;
        n0 = blockIdx.x * 32; k0 = blockIdx.y * 32;
    } else {
        W = w2; WT = wt2; K = 4096; N = 1024;
        int lin = blockIdx.x * 32 + blockIdx.y;   // 0..4095
        n0 = (lin & 31) * 32; k0 = (lin >> 5) * 32;
    }
    int tx = threadIdx.x, ty = threadIdx.y;
#pragma unroll
    for (int j = 0; j < 4; j++)
        t[ty + 8 * j][tx] = W[(size_t)(k0 + ty + 8 * j) * N + n0 + tx];
    __syncthreads();
#pragma unroll
    for (int j = 0; j < 4; j++)
        WT[(size_t)(n0 + ty + 8 * j) * K + k0 + tx] =
            __float2bfloat16_rn(t[tx][ty + 8 * j]);
}

// ---------------- emb = silu(temb) @ W + b  (high-occupancy) ----------------
__global__ __launch_bounds__(256) void emb2_kernel(
    const float* __restrict__ temb,
    const float* __restrict__ w1, const float* __restrict__ b1,
    const float* __restrict__ w2, const float* __restrict__ b2)
{
    __shared__ float st[TEMBC];
    __shared__ float part[8][32];
    int tid = threadIdx.x, lane = tid & 31, wid = tid >> 5;
    for (int i = tid; i < TEMBC; i += 256) {
        float t = temb[i];
        st[i] = t / (1.f + expf(-t));
    }
    __syncthreads();

    int colg = blockIdx.x * 32;
    const float* w; const float* bb; float* out; int col;
    if (colg < 6144) { w = w1; bb = b1; out = g_emb1; col = colg + lane; }
    else             { w = w2; bb = b2; out = g_emb2; col = colg - 6144 + lane; }

    float acc = 0.f;
    int k0 = wid * 64;
#pragma unroll 16
    for (int kk = 0; kk < 64; kk++)
        acc += st[k0 + kk] * w[(size_t)(k0 + kk) * 6144 + col];
    part[wid][lane] = acc;
    __syncthreads();
    if (wid == 0) {
        float s = 0.f;
#pragma unroll
        for (int i = 0; i < 8; i++) s += part[i][lane];
        out[col] = s + bb[col];
    }
}

// ---------------- build unique x rows (bf16 out) ----------------
__global__ __launch_bounds__(256) void build_x_kernel(
    const float* __restrict__ hs, const float* __restrict__ enc,
    const float* __restrict__ g, const float* __restrict__ b)
{
    int row = blockIdx.x;
    const float* src; int sc_off, sh_off;
    if (row < TENC) { src = enc + (size_t)row * DIMC; sc_off = 4096; sh_off = 3072; }
    else            { src = hs + (size_t)(row - TENC) * DIMC; sc_off = 1024; sh_off = 0; }
    int tid = threadIdx.x;
    float x[4]; float s = 0.f, s2 = 0.f;
#pragma unroll
    for (int i = 0; i < 4; i++) {
        x[i] = src[tid + i * 256];
        s += x[i]; s2 += x[i] * x[i];
    }
    block_reduce_2(s, s2);
    float mean = s * (1.f / DIMC);
    float var  = s2 * (1.f / DIMC) - mean * mean;
    float inv  = rsqrtf(var + 1e-5f);
    bf16* dst = g_x + (size_t)row * DIMC;
#pragma unroll
    for (int i = 0; i < 4; i++) {
        int d = tid + i * 256;
        float v = (x[i] - mean) * inv * g[d] + b[d];
        dst[d] = __float2bfloat16_rn(v * (1.f + g_emb1[sc_off + d]) + g_emb1[sh_off + d]);
    }
}

// ---------------- BF16 tensor-core GEMM, 3-stage cp.async ring ----------------
// flags: 1=gelu, 2=bf16 out, 4=ffn2-fused-final-add (f32 RMW on C)
#define SSTR 72
#define STAGE_B 18432
#define GEMM_SMEM_B (6 * STAGE_B)      // 110592 B

__global__ __launch_bounds__(256, 2) void gemm_bf16_kernel(
    const bf16* __restrict__ A, const bf16* __restrict__ B,
    const float* __restrict__ bias, void* __restrict__ Cv,
    int M, int N, int K, int flags)
{
    extern __shared__ bf16 smb[];
    bf16* As0 = smb;
    bf16* Bs0 = smb + 3 * 128 * SSTR;

    int tid = threadIdx.x;
    int bm = blockIdx.y, bn = blockIdx.x;
    int lane = tid & 31, wid = tid >> 5;
    int wm = (wid & 1) * 64, wn = (wid >> 1) * 32;
    int gid = lane >> 2, tig = lane & 3;

    const bf16* Ag = A + (size_t)bm * 128 * K;
    const bf16* Bg = B + (size_t)bn * 128 * K;

    uint32_t smbase = smem_u32(smb);
    uint32_t aBase0 = smbase + (uint32_t)((wm + (lane & 15)) * 144 + (lane >> 4) * 16);
    uint32_t bBase0 = smbase + 3u * STAGE_B +
                      (uint32_t)((wn + (lane & 7) + ((lane >> 4) << 3)) * 144 +
                                 ((lane >> 3) & 1) * 16);

    float acc[4][4][4];
#pragma unroll
    for (int a = 0; a < 4; a++)
#pragma unroll
        for (int b = 0; b < 4; b++)
#pragma unroll
            for (int c = 0; c < 4; c++) acc[a][b][c] = 0.f;

#define LOAD_TILE(kt, buf)                                                         \
    {                                                                              \
        bf16* ad = As0 + (buf) * 128 * SSTR;                                       \
        bf16* bd = Bs0 + (buf) * 128 * SSTR;                                       \
        _Pragma("unroll")                                                          \
        for (int i = 0; i < 4; i++) {                                              \
            int c = tid + i * 256;                                                 \
            int r = c >> 3, kc = (c & 7) << 3;                                     \
            uint32_t dsm = (uint32_t)__cvta_generic_to_shared(ad + r * SSTR + kc); \
            const bf16* s = Ag + (size_t)r * K + (kt) * 64 + kc;                   \
            asm volatile("cp.async.cg.shared.global [%0], [%1], 16;"               \
                         :: "r"(dsm), "l"(s));                                     \
        }                                                                          \
        _Pragma("unroll")                                                          \
        for (int i = 0; i < 4; i++) {                                              \
            int c = tid + i * 256;                                                 \
            int r = c >> 3, kc = (c & 7) << 3;                                     \
            uint32_t dsm = (uint32_t)__cvta_generic_to_shared(bd + r * SSTR + kc); \
            const bf16* s = Bg + (size_t)r * K + (kt) * 64 + kc;                   \
            asm volatile("cp.async.cg.shared.global [%0], [%1], 16;"               \
                         :: "r"(dsm), "l"(s));                                     \
        }                                                                          \
    }

    int ktiles = K / 64;
    LOAD_TILE(0, 0);
    asm volatile("cp.async.commit_group;");
    LOAD_TILE(1, 1);
    asm volatile("cp.async.commit_group;");

    int buf = 0;
    for (int t = 0; t < ktiles; t++) {
        if (t + 1 < ktiles) asm volatile("cp.async.wait_group 1;");
        else                asm volatile("cp.async.wait_group 0;");
        __syncthreads();
        if (t + 2 < ktiles) {
            int nb = (t + 2) % 3;
            LOAD_TILE(t + 2, nb);
            asm volatile("cp.async.commit_group;");
        }

        uint32_t aB = aBase0 + (uint32_t)buf * STAGE_B;
        uint32_t bB = bBase0 + (uint32_t)buf * STAGE_B;
#pragma unroll
        for (int ks = 0; ks < 4; ks++) {
            uint32_t af[4][4], bfr[2][4];
#pragma unroll
            for (int mt = 0; mt < 4; mt++)
                asm volatile(
                    "ldmatrix.sync.aligned.m8n8.x4.shared.b16 {%0,%1,%2,%3}, [%4];"
                    : "=r"(af[mt][0]), "=r"(af[mt][1]), "=r"(af[mt][2]), "=r"(af[mt][3])
                    : "r"(aB + mt * 2304 + ks * 32));
#pragma unroll
            for (int np = 0; np < 2; np++)
                asm volatile(
                    "ldmatrix.sync.aligned.m8n8.x4.shared.b16 {%0,%1,%2,%3}, [%4];"
                    : "=r"(bfr[np][0]), "=r"(bfr[np][1]), "=r"(bfr[np][2]), "=r"(bfr[np][3])
                    : "r"(bB + np * 2304 + ks * 32));
#pragma unroll
            for (int mt = 0; mt < 4; mt++) {
                mma_bf16(acc[mt][0], af[mt], &bfr[0][0]);
                mma_bf16(acc[mt][1], af[mt], &bfr[0][2]);
                mma_bf16(acc[mt][2], af[mt], &bfr[1][0]);
                mma_bf16(acc[mt][3], af[mt], &bfr[1][2]);
            }
        }
        buf = (buf == 2) ? 0 : buf + 1;
    }

    int act = flags & 1, outbf = flags & 2, fin = flags & 4;
#pragma unroll
    for (int mt = 0; mt < 4; mt++) {
        int row = bm * 128 + wm + mt * 16 + gid;
#pragma unroll
        for (int nt = 0; nt < 4; nt++) {
            int col = bn * 128 + wn + nt * 8 + tig * 2;
            float b0 = bias ? bias[col] : 0.f;
            float b1 = bias ? bias[col + 1] : 0.f;
            float v0 = acc[mt][nt][0] + b0, v1 = acc[mt][nt][1] + b1;
            float v2 = acc[mt][nt][2] + b0, v3 = acc[mt][nt][3] + b1;
            if (act) { v0 = gelu_tanh(v0); v1 = gelu_tanh(v1); v2 = gelu_tanh(v2); v3 = gelu_tanh(v3); }
            if (fin) {
                float* C = (float*)Cv;
                int goff  = (row < TENC) ? 5120 : 2048;
                int orow0 = (row < TENC) ? (NTOK + row)     : (row - TENC);
                int orow1 = (row < TENC) ? (NTOK + row + 8) : (row + 8 - TENC);
                float ga = g_emb2[goff + col], gb = g_emb2[goff + col + 1];
                float* p0 = C + (size_t)orow0 * N + col;
                float* p1 = C + (size_t)orow1 * N + col;
                p0[0] += ga * v0; p0[1] += gb * v1;
                p1[0] += ga * v2; p1[1] += gb * v3;
            } else if (outbf) {
                bf16* C = (bf16*)Cv;
                *(uint32_t*)(C + (size_t)row * N + col)       = pack_bf2(v0, v1);
                *(uint32_t*)(C + (size_t)(row + 8) * N + col) = pack_bf2(v2, v3);
            } else {
                float* C = (float*)Cv;
                *(float2*)(C + (size_t)row * N + col)       = make_float2(v0, v1);
                *(float2*)(C + (size_t)(row + 8) * N + col) = make_float2(v2, v3);
            }
        }
    }
}

// ------- per-head LN on q and k in one launch (y: 0=q scale .125, 1=k) --------
__global__ __launch_bounds__(256) void qkln2_kernel(
    bf16* __restrict__ buf,
    const float* __restrict__ qg, const float* __restrict__ qb,
    const float* __restrict__ kg, const float* __restrict__ kb)
{
    int seg  = blockIdx.x * 8 + (threadIdx.x >> 5);
    int lane = threadIdx.x & 31;
    int isk  = blockIdx.y;
    const float* g = isk ? kg : qg;
    const float* b = isk ? kb : qb;
    float scale = isk ? 1.0f : 0.125f;
    bf16* p = buf + (size_t)(seg >> 4) * QKVN + isk * 1024 + (seg & 15) * HD_;
    float x0 = __bfloat162float(p[lane]);
    float x1 = __bfloat162float(p[lane + 32]);
    float s = x0 + x1, s2 = x0 * x0 + x1 * x1;
#pragma unroll
    for (int m = 16; m > 0; m >>= 1) {
        s  += __shfl_xor_sync(0xffffffffu, s,  m);
        s2 += __shfl_xor_sync(0xffffffffu, s2, m);
    }
    float mean = s * (1.f / 64.f);
    float var  = s2 * (1.f / 64.f) - mean * mean;
    float inv  = rsqrtf(var + 1e-6f);
    p[lane]      = __float2bfloat16_rn(((x0 - mean) * inv * g[lane]      + b[lane])      * scale);
    p[lane + 32] = __float2bfloat16_rn(((x1 - mean) * inv * g[lane + 32] + b[lane + 32]) * scale);
}

// ---------------- BF16 flash attention, 3-buffer KV ring, ldmatrix frags ------
#define KVSTAGE (64 * SSTR)
#define ATTN_SMEM_B ((128 * SSTR + 6 * KVSTAGE) * 2)   // 73728 B

__global__ __launch_bounds__(256, 2) void attn_bf16_kernel(
    const bf16* __restrict__ qkv, bf16* __restrict__ o)
{
    extern __shared__ bf16 smb[];
    bf16* Qs  = smb;
    bf16* Ks0 = smb + 128 * SSTR;
    bf16* Vs0 = Ks0 + 3 * KVSTAGE;

    int qt = blockIdx.x, h = blockIdx.y, w = blockIdx.z;
    int tid = threadIdx.x, lane = tid & 31, wid = tid >> 5;
    int gid = lane >> 2, tig = lane & 3;
    int wq0 = wid * 16;
    const size_t obase = (size_t)w * LWIN * DIMC + (size_t)h * HD_;

    size_t qrow0 = (size_t)qt * 128 + (qt ? (size_t)w * SROW : 0);
    const bf16* qg = qkv + qrow0 * QKVN + h * HD_;

#pragma unroll
    for (int i = 0; i < 4; i++) {
        int e = tid + i * 256;
        int r = e >> 3, dc = (e & 7) << 3;
        *(uint4*)(Qs + r * SSTR + dc) = *(const uint4*)(qg + (size_t)r * QKVN + dc);
    }

    // ldmatrix lane bases (A-pattern for Q rows, B-pattern for K kv-rows)
    uint32_t qBase = smem_u32(Qs) +
                     (uint32_t)((wq0 + (lane & 15)) * 144 + (lane >> 4) * 16);
    uint32_t kLane = (uint32_t)(((lane & 7) + ((lane >> 4) << 3)) * 144 +
                                ((lane >> 3) & 1) * 16);

#define KV_LOAD(kt, buf)                                                           \
    {                                                                              \
        size_t krow0 = (size_t)(kt) * 64 + ((kt) >= 2 ? (size_t)w * SROW : 0);     \
        const bf16* kg = qkv + krow0 * QKVN + 1024 + h * HD_;                      \
        const bf16* vg = qkv + krow0 * QKVN + 2048 + h * HD_;                      \
        bf16* kd = Ks0 + (buf) * KVSTAGE;                                          \
        bf16* vd = Vs0 + (buf) * KVSTAGE;                                          \
        _Pragma("unroll")                                                          \
        for (int i = 0; i < 2; i++) {                                              \
            int e = tid + i * 256;                                                 \
            int r = e >> 3, dc = (e & 7) << 3;                                     \
            uint32_t dk = (uint32_t)__cvta_generic_to_shared(kd + r * SSTR + dc);  \
            uint32_t dv = (uint32_t)__cvta_generic_to_shared(vd + r * SSTR + dc);  \
            asm volatile("cp.async.cg.shared.global [%0], [%1], 16;"               \
                         :: "r"(dk), "l"(kg + (size_t)r * QKVN + dc));             \
            asm volatile("cp.async.cg.shared.global [%0], [%1], 16;"               \
                         :: "r"(dv), "l"(vg + (size_t)r * QKVN + dc));             \
        }                                                                          \
    }

    KV_LOAD(0, 0);
    asm volatile("cp.async.commit_group;");
    KV_LOAD(1, 1);
    asm volatile("cp.async.commit_group;");

    float accO[8][4];
#pragma unroll
    for (int nt = 0; nt < 8; nt++)
#pragma unroll
        for (int i = 0; i < 4; i++) accO[nt][i] = 0.f;
    float m0 = -1e30f, m1 = -1e30f, l0 = 0.f, l1 = 0.f;

    int buf = 0;
    for (int kt = 0; kt < 20; kt++) {
        if (kt + 1 < 20) asm volatile("cp.async.wait_group 1;");
        else             asm volatile("cp.async.wait_group 0;");
        __syncthreads();
        if (kt + 2 < 20) {
            int nb = (kt + 2) % 3;
            KV_LOAD(kt + 2, nb);
            asm volatile("cp.async.commit_group;");
        }

        const bf16* Vs = Vs0 + buf * KVSTAGE;
        uint32_t kB = smem_u32(Ks0 + buf * KVSTAGE) + kLane;

        float s[8][4];
#pragma unroll
        for (int nt = 0; nt < 8; nt++)
#pragma unroll
            for (int i = 0; i < 4; i++) s[nt][i] = 0.f;

#pragma unroll
        for (int ks = 0; ks < 4; ks++) {
            uint32_t af[4];
            asm volatile(
                "ldmatrix.sync.aligned.m8n8.x4.shared.b16 {%0,%1,%2,%3}, [%4];"
                : "=r"(af[0]), "=r"(af[1]), "=r"(af[2]), "=r"(af[3])
                : "r"(qBase + ks * 32));
#pragma unroll
            for (int ntp = 0; ntp < 4; ntp++) {
                uint32_t bfr[4];
                asm volatile(
                    "ldmatrix.sync.aligned.m8n8.x4.shared.b16 {%0,%1,%2,%3}, [%4];"
                    : "=r"(bfr[0]), "=r"(bfr[1]), "=r"(bfr[2]), "=r"(bfr[3])
                    : "r"(kB + ntp * 2304 + ks * 32));
                mma_bf16(s[2 * ntp],     af, &bfr[0]);
                mma_bf16(s[2 * ntp + 1], af, &bfr[2]);
            }
        }

        float mx0 = -1e30f, mx1 = -1e30f;
#pragma unroll
        for (int nt = 0; nt < 8; nt++) {
            mx0 = fmaxf(mx0, fmaxf(s[nt][0], s[nt][1]));
            mx1 = fmaxf(mx1, fmaxf(s[nt][2], s[nt][3]));
        }
        mx0 = fmaxf(mx0, __shfl_xor_sync(0xffffffffu, mx0, 1));
        mx0 = fmaxf(mx0, __shfl_xor_sync(0xffffffffu, mx0, 2));
        mx1 = fmaxf(mx1, __shfl_xor_sync(0xffffffffu, mx1, 1));
        mx1 = fmaxf(mx1, __shfl_xor_sync(0xffffffffu, mx1, 2));
        float mn0 = fmaxf(m0, mx0), mn1 = fmaxf(m1, mx1);
        float f0 = __expf(m0 - mn0), f1 = __expf(m1 - mn1);
        m0 = mn0; m1 = mn1;
        float sum0 = 0.f, sum1 = 0.f;
#pragma unroll
        for (int nt = 0; nt < 8; nt++) {
            s[nt][0] = __expf(s[nt][0] - mn0);
            s[nt][1] = __expf(s[nt][1] - mn0);
            s[nt][2] = __expf(s[nt][2] - mn1);
            s[nt][3] = __expf(s[nt][3] - mn1);
            sum0 += s[nt][0] + s[nt][1];
            sum1 += s[nt][2] + s[nt][3];
        }
        sum0 += __shfl_xor_sync(0xffffffffu, sum0, 1);
        sum0 += __shfl_xor_sync(0xffffffffu, sum0, 2);
        sum1 += __shfl_xor_sync(0xffffffffu, sum1, 1);
        sum1 += __shfl_xor_sync(0xffffffffu, sum1, 2);
        l0 = l0 * f0 + sum0;
        l1 = l1 * f1 + sum1;
#pragma unroll
        for (int nt = 0; nt < 8; nt++) {
            accO[nt][0] *= f0; accO[nt][1] *= f0;
            accO[nt][2] *= f1; accO[nt][3] *= f1;
        }

#pragma unroll
        for (int kc = 0; kc < 4; kc++) {
            uint32_t aP[4];
            aP[0] = pack_bf2(s[2 * kc][0],     s[2 * kc][1]);
            aP[1] = pack_bf2(s[2 * kc][2],     s[2 * kc][3]);
            aP[2] = pack_bf2(s[2 * kc + 1][0], s[2 * kc + 1][1]);
            aP[3] = pack_bf2(s[2 * kc + 1][2], s[2 * kc + 1][3]);
#pragma unroll
            for (int ntp = 0; ntp < 4; ntp++) {
                int row = kc * 16 + ((lane >> 3) & 1) * 8 + (lane & 7);
                int col = ntp * 16 + (lane >> 4) * 8;
                uint32_t smaddr = smem_u32(Vs + row * SSTR + col);
                uint32_t b0, b1, b2, b3;
                asm volatile(
                    "ldmatrix.sync.aligned.m8n8.x4.trans.shared.b16 {%0,%1,%2,%3}, [%4];"
                    : "=r"(b0), "=r"(b1), "=r"(b2), "=r"(b3) : "r"(smaddr));
                uint32_t blo[2] = {b0, b1}, bhi[2] = {b2, b3};
                mma_bf16(accO[2 * ntp],     aP, blo);
                mma_bf16(accO[2 * ntp + 1], aP, bhi);
            }
        }
        buf = (buf == 2) ? 0 : buf + 1;
    }

    float il0 = 1.f / l0, il1 = 1.f / l1;
    int row0 = qt * 128 + wq0 + gid;
#pragma unroll
    for (int nt = 0; nt < 8; nt++) {
        int col = nt * 8 + tig * 2;
        *(uint32_t*)(o + obase + (size_t)row0 * DIMC + col) =
            pack_bf2(accO[nt][0] * il0, accO[nt][1] * il0);
        *(uint32_t*)(o + obase + (size_t)(row0 + 8) * DIMC + col) =
            pack_bf2(accO[nt][2] * il1, accO[nt][3] * il1);
    }
}

// ------- blend attention outputs across windows (before wo) -------------------
__global__ __launch_bounds__(256) void blend_ao_kernel()
{
    int row = blockIdx.x;            // 0..MFF-1
    int tid = threadIdx.x;
    bf16* dst = g_x + (size_t)row * DIMC;
    if (row < TENC) {
#pragma unroll
        for (int i = 0; i < 4; i++) {
            int d = tid + i * 256;
            float a = 0.f;
#pragma unroll
            for (int w = 0; w < WQN; w++)
                a += __bfloat162float(g_ao[((size_t)w * LWIN + row) * DIMC + d]);
            dst[d] = __float2bfloat16_rn(a * 0.2f);
        }
    } else {
        int gdx = row - TENC;
        int blk = gdx / SROW;
        float acc[4] = {0.f, 0.f, 0.f, 0.f};
        float wsum = 0.f;
#pragma unroll
        for (int dw = -1; dw <= 0; dw++) {
            int w = blk + dw;
            if (w < 0 || w > 4) continue;
            int lv = gdx - w * SROW;
            float wt = c_pyr[lv / 144];
            wsum += wt;
            const bf16* op = g_ao + ((size_t)w * LWIN + TENC + lv) * DIMC;
#pragma unroll
            for (int i = 0; i < 4; i++)
                acc[i] += wt * __bfloat162float(op[tid + i * 256]);
        }
        float inv = 1.f / wsum;
#pragma unroll
        for (int i = 0; i < 4; i++)
            dst[tid + i * 256] = __float2bfloat16_rn(acc[i] * inv);
    }
}

// ------- post-wo combine: residual + LN2 -> out and ffin ----------------------
__global__ __launch_bounds__(256) void combine_post_kernel(
    const float* __restrict__ hs, const float* __restrict__ enc,
    float* __restrict__ out, const float* __restrict__ g, const float* __restrict__ b)
{
    int row = blockIdx.x;            // 0..MFF-1 (o2 row)
    int tid = threadIdx.x;
    const float* o2 = g_o2 + (size_t)row * DIMC;
    const float* src; float* outp; int gate_off, sc_off, sh_off;
    if (row < TENC) {
        src = enc + (size_t)row * DIMC;
        outp = out + (size_t)(NTOK + row) * DIMC;
        gate_off = 5120; sc_off = 4096; sh_off = 3072;
    } else {
        int gdx = row - TENC;
        src = hs + (size_t)gdx * DIMC;
        outp = out + (size_t)gdx * DIMC;
        gate_off = 2048; sc_off = 1024; sh_off = 0;
    }
    float r[4]; float s = 0.f, s2 = 0.f;
#pragma unroll
    for (int i = 0; i < 4; i++) {
        int d = tid + i * 256;
        r[i] = src[d] + g_emb1[gate_off + d] * o2[d];
        outp[d] = r[i];
        s += r[i]; s2 += r[i] * r[i];
    }
    block_reduce_2(s, s2);
    float mean = s * (1.f / DIMC);
    float var  = s2 * (1.f / DIMC) - mean * mean;
    float inv2 = rsqrtf(var + 1e-5f);
    bf16* dst = g_ffin + (size_t)row * DIMC;
#pragma unroll
    for (int i = 0; i < 4; i++) {
        int d = tid + i * 256;
        float v = (r[i] - mean) * inv2 * g[d] + b[d];
        dst[d] = __float2bfloat16_rn(v * (1.f + g_emb2[sc_off + d]) + g_emb2[sh_off + d]);
    }
}

// ---------------- host side ----------------
static void launch_gemm(const bf16* A, const bf16* B, const float* bias,
                        void* C, int M, int N, int K, int flags)
{
    dim3 grid(N / 128, M / 128);
    gemm_bf16_kernel<<<grid, 256, GEMM_SMEM_B>>>(A, B, bias, C, M, N, K, flags);
}

extern "C" void kernel_launch(void* const* d_in, const int* in_sizes, int n_in,
                              void* d_out, int out_size)
{
    const float* hs    = (const float*)d_in[0];
    const float* enc   = (const float*)d_in[1];
    const float* temb  = (const float*)d_in[2];
    const float* n1w   = (const float*)d_in[3];
    const float* n1b   = (const float*)d_in[4];
    const float* n1g   = (const float*)d_in[5];
    const float* n1bb  = (const float*)d_in[6];
    const float* wq    = (const float*)d_in[7];
    const float* wk    = (const float*)d_in[8];
    const float* wv    = (const float*)d_in[9];
    const float* nqg   = (const float*)d_in[10];
    const float* nqb   = (const float*)d_in[11];
    const float* nkg   = (const float*)d_in[12];
    const float* nkb   = (const float*)d_in[13];
    const float* wo    = (const float*)d_in[14];
    const float* bo    = (const float*)d_in[15];
    const float* n2w   = (const float*)d_in[16];
    const float* n2b   = (const float*)d_in[17];
    const float* n2g   = (const float*)d_in[18];
    const float* n2bb  = (const float*)d_in[19];
    const float* ffw1  = (const float*)d_in[20];
    const float* ffb1  = (const float*)d_in[21];
    const float* ffw2  = (const float*)d_in[22];
    const float* ffb2  = (const float*)d_in[23];
    (void)in_sizes; (void)n_in;

    float* out = (float*)d_out;
    (void)out_size;

    bf16 *p_x, *p_qkv, *p_ao, *p_ffin, *p_h1, *p_wt;
    float *p_o2;
    cudaGetSymbolAddress((void**)&p_x,    g_x);
    cudaGetSymbolAddress((void**)&p_qkv,  g_qkv);
    cudaGetSymbolAddress((void**)&p_ao,   g_ao);
    cudaGetSymbolAddress((void**)&p_o2,   g_o2);
    cudaGetSymbolAddress((void**)&p_ffin, g_ffin);
    cudaGetSymbolAddress((void**)&p_h1,   g_h1);
    cudaGetSymbolAddress((void**)&p_wt,   g_wt);

    bf16* wtqkv = p_wt;                       // [3072][1024] (wq^T|wk^T|wv^T)
    bf16* wtwo  = p_wt + (size_t)3 * MEG;     // [1024][1024]
    bf16* wtw1  = p_wt + (size_t)4 * MEG;     // [4096][1024]
    bf16* wtw2  = p_wt + (size_t)8 * MEG;     // [1024][4096]

    cudaFuncSetAttribute(attn_bf16_kernel, cudaFuncAttributeMaxDynamicSharedMemorySize, ATTN_SMEM_B);
    cudaFuncSetAttribute(gemm_bf16_kernel, cudaFuncAttributeMaxDynamicSharedMemorySize, GEMM_SMEM_B);

    // 0. weight prep
    dim3 tb(32, 8);
    round_wT4_kernel<<<dim3(32, 32, 4), tb>>>(wq, wk, wv, wo, wtqkv);
    round_wT2_kernel<<<dim3(128, 32, 2), tb>>>(ffw1, wtw1, ffw2, wtw2);

    // 1. modulation embeddings
    emb2_kernel<<<384, 256>>>(temb, n1w, n1b, n2w, n2b);
    // 2. unique x rows (bf16)
    build_x_kernel<<<MFF, 256>>>(hs, enc, n1g, n1bb);
    // 3. fused QKV projection -> bf16
    launch_gemm(p_x, wtqkv, nullptr, p_qkv, MFF, QKVN, DIMC, 2);
    // 4. per-head LN on q (x0.125 folded) and k, one launch
    qkln2_kernel<<<dim3(MFF * HEADS_ / 8, 2), 256>>>(p_qkv, nqg, nqb, nkg, nkb);
    // 5. attention (3-buffer KV ring, ldmatrix fragments)
    attn_bf16_kernel<<<dim3(LWIN / 128, HEADS_, WQN), 256, ATTN_SMEM_B>>>(p_qkv, p_ao);
    // 6. blend windows BEFORE wo (row-linear commute), then wo on 3584 rows
    blend_ao_kernel<<<MFF, 256>>>();
    launch_gemm(p_x, wtwo, bo, p_o2, MFF, DIMC, DIMC, 0);
    // 7. residual + LN2 -> out, ffin
    combine_post_kernel<<<MFF, 256>>>(hs, enc, out, n2g, n2bb);
    // 8. FFN; ffn2 fuses final gated residual into out
    launch_gemm(p_ffin, wtw1, ffb1, p_h1, MFF, 4096, DIMC, 1 | 2);
    launch_gemm(p_h1, wtw2, ffb2, out, MFF, DIMC, 4096, 4);
}

// round 16
// speedup vs baseline: 1.0227x; 1.0088x over previous
#include <cuda_runtime.h>
#include <cuda_bf16.h>
#include <math.h>
#include <stdint.h>

typedef __nv_bfloat16 bf16;

// ---------------- constants ----------------
#define DIMC   1024
#define TEMBC  512
#define NTOK   3456
#define TENC   128
#define WQN    5
#define LWIN   1280
#define SROW   576
#define MQ     6400
#define MFF    3584
#define HEADS_ 16
#define HD_    64
#define QKVN   3072
#define MEG    1048576

// ---------------- device scratch ----------------
__device__ float g_emb1[6144];
__device__ float g_emb2[6144];
__device__ bf16  g_x   [(size_t)MFF * DIMC];   // x rows; later reused as blended ao
__device__ bf16  g_qkv [(size_t)MFF * QKVN];
__device__ bf16  g_ao  [(size_t)MQ * DIMC];
__device__ float g_o2  [(size_t)MFF * DIMC];
__device__ bf16  g_ffin[(size_t)MFF * DIMC];
__device__ bf16  g_h1  [(size_t)MFF * 4096];
__device__ bf16  g_wt  [(size_t)12 * MEG];     // qkv^T(3M), wo^T(1M), w1^T(4M), w2^T(4M)

__constant__ float c_pyr[8] = {1.f,2.f,3.f,4.f,4.f,3.f,2.f,1.f};

// ---------------- helpers ----------------
__device__ __forceinline__ uint32_t pack_bf2(float lo, float hi) {
    uint32_t r;
    asm("cvt.rn.bf16x2.f32 %0, %1, %2;" : "=r"(r) : "f"(hi), "f"(lo));
    return r;
}

__device__ __forceinline__ void bf4_to_f4(uint2 u, float* f) {
    __nv_bfloat162 a = *reinterpret_cast<__nv_bfloat162*>(&u.x);
    __nv_bfloat162 b = *reinterpret_cast<__nv_bfloat162*>(&u.y);
    f[0] = __low2float(a); f[1] = __high2float(a);
    f[2] = __low2float(b); f[3] = __high2float(b);
}

__device__ __forceinline__ uint32_t smem_u32(const void* p) {
    return (uint32_t)__cvta_generic_to_shared(p);
}

__device__ __forceinline__ void block_reduce_2(float &s, float &s2) {
    __shared__ float ra[8], rb[8];
#pragma unroll
    for (int m = 16; m > 0; m >>= 1) {
        s  += __shfl_xor_sync(0xffffffffu, s,  m);
        s2 += __shfl_xor_sync(0xffffffffu, s2, m);
    }
    int wid = threadIdx.x >> 5;
    if ((threadIdx.x & 31) == 0) { ra[wid] = s; rb[wid] = s2; }
    __syncthreads();
    s  = ra[0]+ra[1]+ra[2]+ra[3]+ra[4]+ra[5]+ra[6]+ra[7];
    s2 = rb[0]+rb[1]+rb[2]+rb[3]+rb[4]+rb[5]+rb[6]+rb[7];
    __syncthreads();
}

__device__ __forceinline__ float tanh_fast(float x) {
    float y;
    asm("tanh.approx.f32 %0, %1;" : "=f"(y) : "f"(x));
    return y;
}

__device__ __forceinline__ float gelu_tanh(float x) {
    float x3 = x * x * x;
    return 0.5f * x * (1.f + tanh_fast(0.79788456080286535588f * (x + 0.044715f * x3)));
}

__device__ __forceinline__ void mma_bf16(float* d, const uint32_t* a, const uint32_t* b) {
    asm volatile(
        "mma.sync.aligned.m16n8k16.row.col.f32.bf16.bf16.f32 "
        "{%0,%1,%2,%3}, {%4,%5,%6,%7}, {%8,%9}, {%0,%1,%2,%3};"
        : "+f"(d[0]), "+f"(d[1]), "+f"(d[2]), "+f"(d[3])
        : "r"(a[0]), "r"(a[1]), "r"(a[2]), "r"(a[3]), "r"(b[0]), "r"(b[1]));
}

// ---------------- weight prep: transpose + round to bf16 ----------------
__global__ __launch_bounds__(256) void round_wT4_kernel(
    const float* __restrict__ w0, const float* __restrict__ w1,
    const float* __restrict__ w2, const float* __restrict__ w3,
    bf16* __restrict__ dst)
{
    __shared__ float t[32][33];
    int z = blockIdx.z;
    const float* W = (z == 0) ? w0 : (z == 1) ? w1 : (z == 2) ? w2 : w3;
    bf16* WT = dst + (size_t)z * MEG;
    int n0 = blockIdx.x * 32, k0 = blockIdx.y * 32;
    int tx = threadIdx.x, ty = threadIdx.y;
#pragma unroll
    for (int j = 0; j < 4; j++)
        t[ty + 8 * j][tx] = W[(size_t)(k0 + ty + 8 * j) * 1024 + n0 + tx];
    __syncthreads();
#pragma unroll
    for (int j = 0; j < 4; j++)
        WT[(size_t)(n0 + ty + 8 * j) * 1024 + k0 + tx] =
            __float2bfloat16_rn(t[tx][ty + 8 * j]);
}

__global__ __launch_bounds__(256) void round_wT2_kernel(
    const float* __restrict__ w1, bf16* __restrict__ wt1,
    const float* __restrict__ w2, bf16* __restrict__ wt2)
{
    __shared__ float t[32][33];
    const float* W; bf16* WT; int K, N, n0, k0;
    if (blockIdx.z == 0) {
        W = w1; WT = wt1; K = 1024; N = 4096;
        n0 = blockIdx.x * 32; k0 = blockIdx.y * 32;
    } else {
        W = w2; WT = wt2; K = 4096; N = 1024;
        int lin = blockIdx.x * 32 + blockIdx.y;   // 0..4095
        n0 = (lin & 31) * 32; k0 = (lin >> 5) * 32;
    }
    int tx = threadIdx.x, ty = threadIdx.y;
#pragma unroll
    for (int j = 0; j < 4; j++)
        t[ty + 8 * j][tx] = W[(size_t)(k0 + ty + 8 * j) * N + n0 + tx];
    __syncthreads();
#pragma unroll
    for (int j = 0; j < 4; j++)
        WT[(size_t)(n0 + ty + 8 * j) * K + k0 + tx] =
            __float2bfloat16_rn(t[tx][ty + 8 * j]);
}

// ---------------- emb = silu(temb) @ W + b  (high-occupancy) ----------------
__global__ __launch_bounds__(256) void emb2_kernel(
    const float* __restrict__ temb,
    const float* __restrict__ w1, const float* __restrict__ b1,
    const float* __restrict__ w2, const float* __restrict__ b2)
{
    __shared__ float st[TEMBC];
    __shared__ float part[8][32];
    int tid = threadIdx.x, lane = tid & 31, wid = tid >> 5;
    for (int i = tid; i < TEMBC; i += 256) {
        float t = temb[i];
        st[i] = t / (1.f + expf(-t));
    }
    __syncthreads();

    int colg = blockIdx.x * 32;
    const float* w; const float* bb; float* out; int col;
    if (colg < 6144) { w = w1; bb = b1; out = g_emb1; col = colg + lane; }
    else             { w = w2; bb = b2; out = g_emb2; col = colg - 6144 + lane; }

    float acc = 0.f;
    int k0 = wid * 64;
#pragma unroll 16
    for (int kk = 0; kk < 64; kk++)
        acc += st[k0 + kk] * w[(size_t)(k0 + kk) * 6144 + col];
    part[wid][lane] = acc;
    __syncthreads();
    if (wid == 0) {
        float s = 0.f;
#pragma unroll
        for (int i = 0; i < 8; i++) s += part[i][lane];
        out[col] = s + bb[col];
    }
}

// ---------------- build unique x rows (vectorized, bf16 out) ------------------
__global__ __launch_bounds__(256) void build_x_kernel(
    const float* __restrict__ hs, const float* __restrict__ enc,
    const float* __restrict__ g, const float* __restrict__ b)
{
    int row = blockIdx.x;
    const float* src; int sc_off, sh_off;
    if (row < TENC) { src = enc + (size_t)row * DIMC; sc_off = 4096; sh_off = 3072; }
    else            { src = hs + (size_t)(row - TENC) * DIMC; sc_off = 1024; sh_off = 0; }
    int d0 = threadIdx.x * 4;
    float4 x4 = *(const float4*)(src + d0);
    float s  = x4.x + x4.y + x4.z + x4.w;
    float s2 = x4.x * x4.x + x4.y * x4.y + x4.z * x4.z + x4.w * x4.w;
    block_reduce_2(s, s2);
    float mean = s * (1.f / DIMC);
    float var  = s2 * (1.f / DIMC) - mean * mean;
    float inv  = rsqrtf(var + 1e-5f);
    float4 g4  = *(const float4*)(g + d0);
    float4 b4  = *(const float4*)(b + d0);
    float4 sc4 = *(const float4*)(g_emb1 + sc_off + d0);
    float4 sh4 = *(const float4*)(g_emb1 + sh_off + d0);
    float v0 = ((x4.x - mean) * inv * g4.x + b4.x) * (1.f + sc4.x) + sh4.x;
    float v1 = ((x4.y - mean) * inv * g4.y + b4.y) * (1.f + sc4.y) + sh4.y;
    float v2 = ((x4.z - mean) * inv * g4.z + b4.z) * (1.f + sc4.z) + sh4.z;
    float v3 = ((x4.w - mean) * inv * g4.w + b4.w) * (1.f + sc4.w) + sh4.w;
    uint2 o = make_uint2(pack_bf2(v0, v1), pack_bf2(v2, v3));
    *(uint2*)(g_x + (size_t)row * DIMC + d0) = o;
}

// ---------------- BF16 tensor-core GEMM, 3-stage cp.async ring ----------------
// flags: 1=gelu, 2=bf16 out, 4=ffn2-fused-final-add (f32 RMW on C)
#define SSTR 72
#define STAGE_B 18432
#define GEMM_SMEM_B (6 * STAGE_B)      // 110592 B

__global__ __launch_bounds__(256, 2) void gemm_bf16_kernel(
    const bf16* __restrict__ A, const bf16* __restrict__ B,
    const float* __restrict__ bias, void* __restrict__ Cv,
    int M, int N, int K, int flags)
{
    extern __shared__ bf16 smb[];
    bf16* As0 = smb;
    bf16* Bs0 = smb + 3 * 128 * SSTR;

    int tid = threadIdx.x;
    int bm = blockIdx.y, bn = blockIdx.x;
    int lane = tid & 31, wid = tid >> 5;
    int wm = (wid & 1) * 64, wn = (wid >> 1) * 32;
    int gid = lane >> 2, tig = lane & 3;

    const bf16* Ag = A + (size_t)bm * 128 * K;
    const bf16* Bg = B + (size_t)bn * 128 * K;

    uint32_t smbase = smem_u32(smb);
    uint32_t aBase0 = smbase + (uint32_t)((wm + (lane & 15)) * 144 + (lane >> 4) * 16);
    uint32_t bBase0 = smbase + 3u * STAGE_B +
                      (uint32_t)((wn + (lane & 7) + ((lane >> 4) << 3)) * 144 +
                                 ((lane >> 3) & 1) * 16);

    float acc[4][4][4];
#pragma unroll
    for (int a = 0; a < 4; a++)
#pragma unroll
        for (int b = 0; b < 4; b++)
#pragma unroll
            for (int c = 0; c < 4; c++) acc[a][b][c] = 0.f;

#define LOAD_TILE(kt, buf)                                                         \
    {                                                                              \
        bf16* ad = As0 + (buf) * 128 * SSTR;                                       \
        bf16* bd = Bs0 + (buf) * 128 * SSTR;                                       \
        _Pragma("unroll")                                                          \
        for (int i = 0; i < 4; i++) {                                              \
            int c = tid + i * 256;                                                 \
            int r = c >> 3, kc = (c & 7) << 3;                                     \
            uint32_t dsm = (uint32_t)__cvta_generic_to_shared(ad + r * SSTR + kc); \
            const bf16* s = Ag + (size_t)r * K + (kt) * 64 + kc;                   \
            asm volatile("cp.async.cg.shared.global [%0], [%1], 16;"               \
                         :: "r"(dsm), "l"(s));                                     \
        }                                                                          \
        _Pragma("unroll")                                                          \
        for (int i = 0; i < 4; i++) {                                              \
            int c = tid + i * 256;                                                 \
            int r = c >> 3, kc = (c & 7) << 3;                                     \
            uint32_t dsm = (uint32_t)__cvta_generic_to_shared(bd + r * SSTR + kc); \
            const bf16* s = Bg + (size_t)r * K + (kt) * 64 + kc;                   \
            asm volatile("cp.async.cg.shared.global [%0], [%1], 16;"               \
                         :: "r"(dsm), "l"(s));                                     \
        }                                                                          \
    }

    int ktiles = K / 64;
    LOAD_TILE(0, 0);
    asm volatile("cp.async.commit_group;");
    LOAD_TILE(1, 1);
    asm volatile("cp.async.commit_group;");

    int buf = 0;
    for (int t = 0; t < ktiles; t++) {
        if (t + 1 < ktiles) asm volatile("cp.async.wait_group 1;");
        else                asm volatile("cp.async.wait_group 0;");
        __syncthreads();
        if (t + 2 < ktiles) {
            int nb = (t + 2) % 3;
            LOAD_TILE(t + 2, nb);
            asm volatile("cp.async.commit_group;");
        }

        uint32_t aB = aBase0 + (uint32_t)buf * STAGE_B;
        uint32_t bB = bBase0 + (uint32_t)buf * STAGE_B;
#pragma unroll
        for (int ks = 0; ks < 4; ks++) {
            uint32_t af[4][4], bfr[2][4];
#pragma unroll
            for (int mt = 0; mt < 4; mt++)
                asm volatile(
                    "ldmatrix.sync.aligned.m8n8.x4.shared.b16 {%0,%1,%2,%3}, [%4];"
                    : "=r"(af[mt][0]), "=r"(af[mt][1]), "=r"(af[mt][2]), "=r"(af[mt][3])
                    : "r"(aB + mt * 2304 + ks * 32));
#pragma unroll
            for (int np = 0; np < 2; np++)
                asm volatile(
                    "ldmatrix.sync.aligned.m8n8.x4.shared.b16 {%0,%1,%2,%3}, [%4];"
                    : "=r"(bfr[np][0]), "=r"(bfr[np][1]), "=r"(bfr[np][2]), "=r"(bfr[np][3])
                    : "r"(bB + np * 2304 + ks * 32));
#pragma unroll
            for (int mt = 0; mt < 4; mt++) {
                mma_bf16(acc[mt][0], af[mt], &bfr[0][0]);
                mma_bf16(acc[mt][1], af[mt], &bfr[0][2]);
                mma_bf16(acc[mt][2], af[mt], &bfr[1][0]);
                mma_bf16(acc[mt][3], af[mt], &bfr[1][2]);
            }
        }
        buf = (buf == 2) ? 0 : buf + 1;
    }

    int act = flags & 1, outbf = flags & 2, fin = flags & 4;
#pragma unroll
    for (int mt = 0; mt < 4; mt++) {
        int row = bm * 128 + wm + mt * 16 + gid;
#pragma unroll
        for (int nt = 0; nt < 4; nt++) {
            int col = bn * 128 + wn + nt * 8 + tig * 2;
            float b0 = bias ? bias[col] : 0.f;
            float b1 = bias ? bias[col + 1] : 0.f;
            float v0 = acc[mt][nt][0] + b0, v1 = acc[mt][nt][1] + b1;
            float v2 = acc[mt][nt][2] + b0, v3 = acc[mt][nt][3] + b1;
            if (act) { v0 = gelu_tanh(v0); v1 = gelu_tanh(v1); v2 = gelu_tanh(v2); v3 = gelu_tanh(v3); }
            if (fin) {
                float* C = (float*)Cv;
                int goff  = (row < TENC) ? 5120 : 2048;
                int orow0 = (row < TENC) ? (NTOK + row)     : (row - TENC);
                int orow1 = (row < TENC) ? (NTOK + row + 8) : (row + 8 - TENC);
                float ga = g_emb2[goff + col], gb = g_emb2[goff + col + 1];
                float* p0 = C + (size_t)orow0 * N + col;
                float* p1 = C + (size_t)orow1 * N + col;
                p0[0] += ga * v0; p0[1] += gb * v1;
                p1[0] += ga * v2; p1[1] += gb * v3;
            } else if (outbf) {
                bf16* C = (bf16*)Cv;
                *(uint32_t*)(C + (size_t)row * N + col)       = pack_bf2(v0, v1);
                *(uint32_t*)(C + (size_t)(row + 8) * N + col) = pack_bf2(v2, v3);
            } else {
                float* C = (float*)Cv;
                *(float2*)(C + (size_t)row * N + col)       = make_float2(v0, v1);
                *(float2*)(C + (size_t)(row + 8) * N + col) = make_float2(v2, v3);
            }
        }
    }
}

// ------- per-head LN on q and k, packed lanes (y: 0=q scale .125, 1=k) --------
__global__ __launch_bounds__(256) void qkln2_kernel(
    bf16* __restrict__ buf,
    const float* __restrict__ qg, const float* __restrict__ qb,
    const float* __restrict__ kg, const float* __restrict__ kb)
{
    int seg  = blockIdx.x * 8 + (threadIdx.x >> 5);
    int lane = threadIdx.x & 31;
    int isk  = blockIdx.y;
    const float* g = isk ? kg : qg;
    const float* b = isk ? kb : qb;
    float scale = isk ? 1.0f : 0.125f;
    bf16* p = buf + (size_t)(seg >> 4) * QKVN + isk * 1024 + (seg & 15) * HD_;
    uint32_t pk = *(const uint32_t*)(p + 2 * lane);
    __nv_bfloat162 h = *reinterpret_cast<__nv_bfloat162*>(&pk);
    float x0 = __low2float(h), x1 = __high2float(h);
    float s = x0 + x1, s2 = x0 * x0 + x1 * x1;
#pragma unroll
    for (int m = 16; m > 0; m >>= 1) {
        s  += __shfl_xor_sync(0xffffffffu, s,  m);
        s2 += __shfl_xor_sync(0xffffffffu, s2, m);
    }
    float mean = s * (1.f / 64.f);
    float var  = s2 * (1.f / 64.f) - mean * mean;
    float inv  = rsqrtf(var + 1e-6f);
    float2 gg = *(const float2*)(g + 2 * lane);
    float2 bb = *(const float2*)(b + 2 * lane);
    float v0 = ((x0 - mean) * inv * gg.x + bb.x) * scale;
    float v1 = ((x1 - mean) * inv * gg.y + bb.y) * scale;
    *(uint32_t*)(p + 2 * lane) = pack_bf2(v0, v1);
}

// ---------------- BF16 flash attention, 3-buffer KV ring, ldmatrix frags ------
#define KVSTAGE (64 * SSTR)
#define ATTN_SMEM_B ((128 * SSTR + 6 * KVSTAGE) * 2)   // 73728 B

__global__ __launch_bounds__(256, 2) void attn_bf16_kernel(
    const bf16* __restrict__ qkv, bf16* __restrict__ o)
{
    extern __shared__ bf16 smb[];
    bf16* Qs  = smb;
    bf16* Ks0 = smb + 128 * SSTR;
    bf16* Vs0 = Ks0 + 3 * KVSTAGE;

    int qt = blockIdx.x, h = blockIdx.y, w = blockIdx.z;
    int tid = threadIdx.x, lane = tid & 31, wid = tid >> 5;
    int gid = lane >> 2, tig = lane & 3;
    int wq0 = wid * 16;
    const size_t obase = (size_t)w * LWIN * DIMC + (size_t)h * HD_;

    size_t qrow0 = (size_t)qt * 128 + (qt ? (size_t)w * SROW : 0);
    const bf16* qg = qkv + qrow0 * QKVN + h * HD_;

#pragma unroll
    for (int i = 0; i < 4; i++) {
        int e = tid + i * 256;
        int r = e >> 3, dc = (e & 7) << 3;
        *(uint4*)(Qs + r * SSTR + dc) = *(const uint4*)(qg + (size_t)r * QKVN + dc);
    }

    uint32_t qBase = smem_u32(Qs) +
                     (uint32_t)((wq0 + (lane & 15)) * 144 + (lane >> 4) * 16);
    uint32_t kLane = (uint32_t)(((lane & 7) + ((lane >> 4) << 3)) * 144 +
                                ((lane >> 3) & 1) * 16);

#define KV_LOAD(kt, buf)                                                           \
    {                                                                              \
        size_t krow0 = (size_t)(kt) * 64 + ((kt) >= 2 ? (size_t)w * SROW : 0);     \
        const bf16* kg = qkv + krow0 * QKVN + 1024 + h * HD_;                      \
        const bf16* vg = qkv + krow0 * QKVN + 2048 + h * HD_;                      \
        bf16* kd = Ks0 + (buf) * KVSTAGE;                                          \
        bf16* vd = Vs0 + (buf) * KVSTAGE;                                          \
        _Pragma("unroll")                                                          \
        for (int i = 0; i < 2; i++) {                                              \
            int e = tid + i * 256;                                                 \
            int r = e >> 3, dc = (e & 7) << 3;                                     \
            uint32_t dk = (uint32_t)__cvta_generic_to_shared(kd + r * SSTR + dc);  \
            uint32_t dv = (uint32_t)__cvta_generic_to_shared(vd + r * SSTR + dc);  \
            asm volatile("cp.async.cg.shared.global [%0], [%1], 16;"               \
                         :: "r"(dk), "l"(kg + (size_t)r * QKVN + dc));             \
            asm volatile("cp.async.cg.shared.global [%0], [%1], 16;"               \
                         :: "r"(dv), "l"(vg + (size_t)r * QKVN + dc));             \
        }                                                                          \
    }

    KV_LOAD(0, 0);
    asm volatile("cp.async.commit_group;");
    KV_LOAD(1, 1);
    asm volatile("cp.async.commit_group;");

    float accO[8][4];
#pragma unroll
    for (int nt = 0; nt < 8; nt++)
#pragma unroll
        for (int i = 0; i < 4; i++) accO[nt][i] = 0.f;
    float m0 = -1e30f, m1 = -1e30f, l0 = 0.f, l1 = 0.f;

    int buf = 0;
    for (int kt = 0; kt < 20; kt++) {
        if (kt + 1 < 20) asm volatile("cp.async.wait_group 1;");
        else             asm volatile("cp.async.wait_group 0;");
        __syncthreads();
        if (kt + 2 < 20) {
            int nb = (kt + 2) % 3;
            KV_LOAD(kt + 2, nb);
            asm volatile("cp.async.commit_group;");
        }

        const bf16* Vs = Vs0 + buf * KVSTAGE;
        uint32_t kB = smem_u32(Ks0 + buf * KVSTAGE) + kLane;

        float s[8][4];
#pragma unroll
        for (int nt = 0; nt < 8; nt++)
#pragma unroll
            for (int i = 0; i < 4; i++) s[nt][i] = 0.f;

#pragma unroll
        for (int ks = 0; ks < 4; ks++) {
            uint32_t af[4];
            asm volatile(
                "ldmatrix.sync.aligned.m8n8.x4.shared.b16 {%0,%1,%2,%3}, [%4];"
                : "=r"(af[0]), "=r"(af[1]), "=r"(af[2]), "=r"(af[3])
                : "r"(qBase + ks * 32));
#pragma unroll
            for (int ntp = 0; ntp < 4; ntp++) {
                uint32_t bfr[4];
                asm volatile(
                    "ldmatrix.sync.aligned.m8n8.x4.shared.b16 {%0,%1,%2,%3}, [%4];"
                    : "=r"(bfr[0]), "=r"(bfr[1]), "=r"(bfr[2]), "=r"(bfr[3])
                    : "r"(kB + ntp * 2304 + ks * 32));
                mma_bf16(s[2 * ntp],     af, &bfr[0]);
                mma_bf16(s[2 * ntp + 1], af, &bfr[2]);
            }
        }

        float mx0 = -1e30f, mx1 = -1e30f;
#pragma unroll
        for (int nt = 0; nt < 8; nt++) {
            mx0 = fmaxf(mx0, fmaxf(s[nt][0], s[nt][1]));
            mx1 = fmaxf(mx1, fmaxf(s[nt][2], s[nt][3]));
        }
        mx0 = fmaxf(mx0, __shfl_xor_sync(0xffffffffu, mx0, 1));
        mx0 = fmaxf(mx0, __shfl_xor_sync(0xffffffffu, mx0, 2));
        mx1 = fmaxf(mx1, __shfl_xor_sync(0xffffffffu, mx1, 1));
        mx1 = fmaxf(mx1, __shfl_xor_sync(0xffffffffu, mx1, 2));
        float mn0 = fmaxf(m0, mx0), mn1 = fmaxf(m1, mx1);
        float f0 = __expf(m0 - mn0), f1 = __expf(m1 - mn1);
        m0 = mn0; m1 = mn1;
        float sum0 = 0.f, sum1 = 0.f;
#pragma unroll
        for (int nt = 0; nt < 8; nt++) {
            s[nt][0] = __expf(s[nt][0] - mn0);
            s[nt][1] = __expf(s[nt][1] - mn0);
            s[nt][2] = __expf(s[nt][2] - mn1);
            s[nt][3] = __expf(s[nt][3] - mn1);
            sum0 += s[nt][0] + s[nt][1];
            sum1 += s[nt][2] + s[nt][3];
        }
        sum0 += __shfl_xor_sync(0xffffffffu, sum0, 1);
        sum0 += __shfl_xor_sync(0xffffffffu, sum0, 2);
        sum1 += __shfl_xor_sync(0xffffffffu, sum1, 1);
        sum1 += __shfl_xor_sync(0xffffffffu, sum1, 2);
        l0 = l0 * f0 + sum0;
        l1 = l1 * f1 + sum1;
#pragma unroll
        for (int nt = 0; nt < 8; nt++) {
            accO[nt][0] *= f0; accO[nt][1] *= f0;
            accO[nt][2] *= f1; accO[nt][3] *= f1;
        }

#pragma unroll
        for (int kc = 0; kc < 4; kc++) {
            uint32_t aP[4];
            aP[0] = pack_bf2(s[2 * kc][0],     s[2 * kc][1]);
            aP[1] = pack_bf2(s[2 * kc][2],     s[2 * kc][3]);
            aP[2] = pack_bf2(s[2 * kc + 1][0], s[2 * kc + 1][1]);
            aP[3] = pack_bf2(s[2 * kc + 1][2], s[2 * kc + 1][3]);
#pragma unroll
            for (int ntp = 0; ntp < 4; ntp++) {
                int row = kc * 16 + ((lane >> 3) & 1) * 8 + (lane & 7);
                int col = ntp * 16 + (lane >> 4) * 8;
                uint32_t smaddr = smem_u32(Vs + row * SSTR + col);
                uint32_t b0, b1, b2, b3;
                asm volatile(
                    "ldmatrix.sync.aligned.m8n8.x4.trans.shared.b16 {%0,%1,%2,%3}, [%4];"
                    : "=r"(b0), "=r"(b1), "=r"(b2), "=r"(b3) : "r"(smaddr));
                uint32_t blo[2] = {b0, b1}, bhi[2] = {b2, b3};
                mma_bf16(accO[2 * ntp],     aP, blo);
                mma_bf16(accO[2 * ntp + 1], aP, bhi);
            }
        }
        buf = (buf == 2) ? 0 : buf + 1;
    }

    float il0 = 1.f / l0, il1 = 1.f / l1;
    int row0 = qt * 128 + wq0 + gid;
#pragma unroll
    for (int nt = 0; nt < 8; nt++) {
        int col = nt * 8 + tig * 2;
        *(uint32_t*)(o + obase + (size_t)row0 * DIMC + col) =
            pack_bf2(accO[nt][0] * il0, accO[nt][1] * il0);
        *(uint32_t*)(o + obase + (size_t)(row0 + 8) * DIMC + col) =
            pack_bf2(accO[nt][2] * il1, accO[nt][3] * il1);
    }
}

// ------- blend attention outputs across windows (vectorized) ------------------
__global__ __launch_bounds__(256) void blend_ao_kernel()
{
    int row = blockIdx.x;            // 0..MFF-1
    int d0 = threadIdx.x * 4;
    bf16* dst = g_x + (size_t)row * DIMC;
    float acc[4] = {0.f, 0.f, 0.f, 0.f};
    float f[4];
    if (row < TENC) {
#pragma unroll
        for (int w = 0; w < WQN; w++) {
            uint2 u = *(const uint2*)(g_ao + ((size_t)w * LWIN + row) * DIMC + d0);
            bf4_to_f4(u, f);
#pragma unroll
            for (int i = 0; i < 4; i++) acc[i] += f[i];
        }
        *(uint2*)(dst + d0) = make_uint2(pack_bf2(acc[0] * 0.2f, acc[1] * 0.2f),
                                         pack_bf2(acc[2] * 0.2f, acc[3] * 0.2f));
    } else {
        int gdx = row - TENC;
        int blk = gdx / SROW;
        float wsum = 0.f;
#pragma unroll
        for (int dw = -1; dw <= 0; dw++) {
            int w = blk + dw;
            if (w < 0 || w > 4) continue;
            int lv = gdx - w * SROW;
            float wt = c_pyr[lv / 144];
            wsum += wt;
            uint2 u = *(const uint2*)(g_ao + ((size_t)w * LWIN + TENC + lv) * DIMC + d0);
            bf4_to_f4(u, f);
#pragma unroll
            for (int i = 0; i < 4; i++) acc[i] += wt * f[i];
        }
        float inv = 1.f / wsum;
        *(uint2*)(dst + d0) = make_uint2(pack_bf2(acc[0] * inv, acc[1] * inv),
                                         pack_bf2(acc[2] * inv, acc[3] * inv));
    }
}

// ------- post-wo combine: residual + LN2 -> out and ffin (vectorized) ---------
__global__ __launch_bounds__(256) void combine_post_kernel(
    const float* __restrict__ hs, const float* __restrict__ enc,
    float* __restrict__ out, const float* __restrict__ g, const float* __restrict__ b)
{
    int row = blockIdx.x;            // 0..MFF-1
    int d0 = threadIdx.x * 4;
    const float* o2 = g_o2 + (size_t)row * DIMC;
    const float* src; float* outp; int gate_off, sc_off, sh_off;
    if (row < TENC) {
        src = enc + (size_t)row * DIMC;
        outp = out + (size_t)(NTOK + row) * DIMC;
        gate_off = 5120; sc_off = 4096; sh_off = 3072;
    } else {
        int gdx = row - TENC;
        src = hs + (size_t)gdx * DIMC;
        outp = out + (size_t)gdx * DIMC;
        gate_off = 2048; sc_off = 1024; sh_off = 0;
    }
    float4 s4 = *(const float4*)(src + d0);
    float4 o4 = *(const float4*)(o2 + d0);
    float4 gt4 = *(const float4*)(g_emb1 + gate_off + d0);
    float r0 = s4.x + gt4.x * o4.x;
    float r1 = s4.y + gt4.y * o4.y;
    float r2 = s4.z + gt4.z * o4.z;
    float r3 = s4.w + gt4.w * o4.w;
    *(float4*)(outp + d0) = make_float4(r0, r1, r2, r3);
    float s = r0 + r1 + r2 + r3;
    float s2 = r0 * r0 + r1 * r1 + r2 * r2 + r3 * r3;
    block_reduce_2(s, s2);
    float mean = s * (1.f / DIMC);
    float var  = s2 * (1.f / DIMC) - mean * mean;
    float inv2 = rsqrtf(var + 1e-5f);
    float4 g4  = *(const float4*)(g + d0);
    float4 b4  = *(const float4*)(b + d0);
    float4 sc4 = *(const float4*)(g_emb2 + sc_off + d0);
    float4 sh4 = *(const float4*)(g_emb2 + sh_off + d0);
    float v0 = ((r0 - mean) * inv2 * g4.x + b4.x) * (1.f + sc4.x) + sh4.x;
    float v1 = ((r1 - mean) * inv2 * g4.y + b4.y) * (1.f + sc4.y) + sh4.y;
    float v2 = ((r2 - mean) * inv2 * g4.z + b4.z) * (1.f + sc4.z) + sh4.z;
    float v3 = ((r3 - mean) * inv2 * g4.w + b4.w) * (1.f + sc4.w) + sh4.w;
    *(uint2*)(g_ffin + (size_t)row * DIMC + d0) =
        make_uint2(pack_bf2(v0, v1), pack_bf2(v2, v3));
}

// ---------------- host side ----------------
static void launch_gemm(const bf16* A, const bf16* B, const float* bias,
                        void* C, int M, int N, int K, int flags)
{
    dim3 grid(N / 128, M / 128);
    gemm_bf16_kernel<<<grid, 256, GEMM_SMEM_B>>>(A, B, bias, C, M, N, K, flags);
}

extern "C" void kernel_launch(void* const* d_in, const int* in_sizes, int n_in,
                              void* d_out, int out_size)
{
    const float* hs    = (const float*)d_in[0];
    const float* enc   = (const float*)d_in[1];
    const float* temb  = (const float*)d_in[2];
    const float* n1w   = (const float*)d_in[3];
    const float* n1b   = (const float*)d_in[4];
    const float* n1g   = (const float*)d_in[5];
    const float* n1bb  = (const float*)d_in[6];
    const float* wq    = (const float*)d_in[7];
    const float* wk    = (const float*)d_in[8];
    const float* wv    = (const float*)d_in[9];
    const float* nqg   = (const float*)d_in[10];
    const float* nqb   = (const float*)d_in[11];
    const float* nkg   = (const float*)d_in[12];
    const float* nkb   = (const float*)d_in[13];
    const float* wo    = (const float*)d_in[14];
    const float* bo    = (const float*)d_in[15];
    const float* n2w   = (const float*)d_in[16];
    const float* n2b   = (const float*)d_in[17];
    const float* n2g   = (const float*)d_in[18];
    const float* n2bb  = (const float*)d_in[19];
    const float* ffw1  = (const float*)d_in[20];
    const float* ffb1  = (const float*)d_in[21];
    const float* ffw2  = (const float*)d_in[22];
    const float* ffb2  = (const float*)d_in[23];
    (void)in_sizes; (void)n_in;

    float* out = (float*)d_out;
    (void)out_size;

    bf16 *p_x, *p_qkv, *p_ao, *p_ffin, *p_h1, *p_wt;
    float *p_o2;
    cudaGetSymbolAddress((void**)&p_x,    g_x);
    cudaGetSymbolAddress((void**)&p_qkv,  g_qkv);
    cudaGetSymbolAddress((void**)&p_ao,   g_ao);
    cudaGetSymbolAddress((void**)&p_o2,   g_o2);
    cudaGetSymbolAddress((void**)&p_ffin, g_ffin);
    cudaGetSymbolAddress((void**)&p_h1,   g_h1);
    cudaGetSymbolAddress((void**)&p_wt,   g_wt);

    bf16* wtqkv = p_wt;                       // [3072][1024] (wq^T|wk^T|wv^T)
    bf16* wtwo  = p_wt + (size_t)3 * MEG;     // [1024][1024]
    bf16* wtw1  = p_wt + (size_t)4 * MEG;     // [4096][1024]
    bf16* wtw2  = p_wt + (size_t)8 * MEG;     // [1024][4096]

    cudaFuncSetAttribute(attn_bf16_kernel, cudaFuncAttributeMaxDynamicSharedMemorySize, ATTN_SMEM_B);
    cudaFuncSetAttribute(gemm_bf16_kernel, cudaFuncAttributeMaxDynamicSharedMemorySize, GEMM_SMEM_B);

    // 0. weight prep
    dim3 tb(32, 8);
    round_wT4_kernel<<<dim3(32, 32, 4), tb>>>(wq, wk, wv, wo, wtqkv);
    round_wT2_kernel<<<dim3(128, 32, 2), tb>>>(ffw1, wtw1, ffw2, wtw2);

    // 1. modulation embeddings
    emb2_kernel<<<384, 256>>>(temb, n1w, n1b, n2w, n2b);
    // 2. unique x rows (bf16, vectorized)
    build_x_kernel<<<MFF, 256>>>(hs, enc, n1g, n1bb);
    // 3. fused QKV projection -> bf16
    launch_gemm(p_x, wtqkv, nullptr, p_qkv, MFF, QKVN, DIMC, 2);
    // 4. per-head LN on q (x0.125 folded) and k, packed lanes
    qkln2_kernel<<<dim3(MFF * HEADS_ / 8, 2), 256>>>(p_qkv, nqg, nqb, nkg, nkb);
    // 5. attention (3-buffer KV ring, ldmatrix fragments)
    attn_bf16_kernel<<<dim3(LWIN / 128, HEADS_, WQN), 256, ATTN_SMEM_B>>>(p_qkv, p_ao);
    // 6. blend windows BEFORE wo (row-linear commute), then wo on 3584 rows
    blend_ao_kernel<<<MFF, 256>>>();
    launch_gemm(p_x, wtwo, bo, p_o2, MFF, DIMC, DIMC, 0);
    // 7. residual + LN2 -> out, ffin (vectorized)
    combine_post_kernel<<<MFF, 256>>>(hs, enc, out, n2g, n2bb);
    // 8. FFN; ffn2 fuses final gated residual into out
    launch_gemm(p_ffin, wtw1, ffb1, p_h1, MFF, 4096, DIMC, 1 | 2);
    launch_gemm(p_h1, wtw2, ffb2, out, MFF, DIMC, 4096, 4);
}